// round 1
// baseline (speedup 1.0000x reference)
#include <cuda_runtime.h>
#include <math.h>

#define BB 2
#define NN 4096
#define DIMD 1024
#define HEADS 16
#define DH 64
#define WW 512
#define NW (NN/WW)          // 8
#define INNER 2730
#define GGW 2732            // padded INNER so row stride is 16B-aligned
#define ROWS (BB*NN)        // 8192
#define QKVN (3*HEADS*DH)   // 3072
#define FF1N (2*INNER)      // 5460

// ------------------- scratch (device globals; no allocation) -------------------
__device__ float g_h   [ROWS*DIMD];       // LN1 / LN2 output
__device__ float g_qkv [ROWS*QKVN];
__device__ float g_q   [BB*HEADS*NN*DH];
__device__ float g_k   [BB*HEADS*NN*DH];
__device__ float g_v   [BB*HEADS*NN*DH];
__device__ float g_attn[ROWS*DIMD];
__device__ float g_x1  [ROWS*DIMD];
__device__ float g_u   [ROWS*FF1N];
__device__ float g_gg  [ROWS*GGW];

// ------------------------------- LayerNorm -------------------------------
__global__ __launch_bounds__(256) void ln_kernel(
    const float* __restrict__ X, const float* __restrict__ w,
    const float* __restrict__ b, float* __restrict__ Y)
{
    __shared__ float sa[8], sb[8];
    int row = blockIdx.x;
    int t = threadIdx.x;
    const float4* xr = (const float4*)(X + (size_t)row * DIMD);
    float4 xv = xr[t];
    float s  = xv.x + xv.y + xv.z + xv.w;
    float sq = xv.x*xv.x + xv.y*xv.y + xv.z*xv.z + xv.w*xv.w;

    int lane = t & 31, wrp = t >> 5;
    #pragma unroll
    for (int o = 16; o; o >>= 1) {
        s  += __shfl_xor_sync(0xffffffffu, s,  o);
        sq += __shfl_xor_sync(0xffffffffu, sq, o);
    }
    if (lane == 0) { sa[wrp] = s; sb[wrp] = sq; }
    __syncthreads();
    if (wrp == 0) {
        s  = (lane < 8) ? sa[lane] : 0.f;
        sq = (lane < 8) ? sb[lane] : 0.f;
        #pragma unroll
        for (int o = 4; o; o >>= 1) {
            s  += __shfl_xor_sync(0xffffffffu, s,  o);
            sq += __shfl_xor_sync(0xffffffffu, sq, o);
        }
        if (lane == 0) { sa[0] = s; sb[0] = sq; }
    }
    __syncthreads();
    float mean = sa[0] * (1.f / DIMD);
    float var  = sb[0] * (1.f / DIMD) - mean * mean;
    float inv  = rsqrtf(var + 1e-5f);

    float4 wv = ((const float4*)w)[t];
    float4 out;
    out.x = (xv.x - mean) * inv * wv.x;
    out.y = (xv.y - mean) * inv * wv.y;
    out.z = (xv.z - mean) * inv * wv.z;
    out.w = (xv.w - mean) * inv * wv.w;
    if (b) {
        float4 bv = ((const float4*)b)[t];
        out.x += bv.x; out.y += bv.y; out.z += bv.z; out.w += bv.w;
    }
    ((float4*)(Y + (size_t)row * DIMD))[t] = out;
}

// ----------------------- rotary + head split (+q scale) -----------------------
__global__ __launch_bounds__(512) void rope_kernel(
    const float* __restrict__ QKV, float* __restrict__ Q,
    float* __restrict__ K, float* __restrict__ V)
{
    int row = blockIdx.x;                 // b*N + n
    int b = row >> 12, n = row & (NN - 1);
    int t = threadIdx.x;                  // 512
    const float* base = QKV + (size_t)row * QKVN;

    int h = t >> 5, dj = t & 31;
    // inv = 10000^(-dj/32) exactly as jax computes in fp32
    float inv = powf(10000.f, -(float)dj * (1.f / 32.f));
    float f = (float)n * inv;
    float sn, cs; sincosf(f, &sn, &cs);

    size_t o = ((size_t)(b * HEADS + h) * NN + n) * DH;
    // q (scale by DH^-0.5 = 0.125 after rotary)
    float x1 = base[h * DH + dj];
    float x2 = base[h * DH + dj + 32];
    Q[o + dj]      = (x1 * cs - x2 * sn) * 0.125f;
    Q[o + dj + 32] = (x2 * cs + x1 * sn) * 0.125f;
    // k
    x1 = base[DIMD + h * DH + dj];
    x2 = base[DIMD + h * DH + dj + 32];
    K[o + dj]      = x1 * cs - x2 * sn;
    K[o + dj + 32] = x2 * cs + x1 * sn;
    // v: copy cols t and t+512
    int c0 = t, c1 = t + 512;
    V[((size_t)(b * HEADS + (c0 >> 6)) * NN + n) * DH + (c0 & 63)] = base[2 * DIMD + c0];
    V[((size_t)(b * HEADS + (c1 >> 6)) * NN + n) * DH + (c1 & 63)] = base[2 * DIMD + c1];
}

// --------------------------- windowed attention ---------------------------
// block = 256 threads, handles 64 queries of one (b, h, window, qblock).
// thread (r = t/4, sub = t%4): owns query row r, keys kj = j*4+sub per tile,
// output dims d = d4*16 + sub*4 + dd.
#define SM_STRIDE 68
__global__ __launch_bounds__(256) void attn_kernel(
    const float* __restrict__ Q, const float* __restrict__ K,
    const float* __restrict__ V, float* __restrict__ O)
{
    extern __shared__ float sm[];
    float* Qs = sm;
    float* Ks = sm + 64 * SM_STRIDE;
    float* Vs = sm + 2 * 64 * SM_STRIDE;

    int idx = blockIdx.x;
    int qb = idx & 7;
    int wi = (idx >> 3) & 7;
    int h  = (idx >> 6) & 15;
    int b  = idx >> 10;
    int t  = threadIdx.x;

    const size_t bh = ((size_t)b * HEADS + h) * NN;
    int n0 = wi * WW + qb * 64;

    // load Q tile [64 x 64] into swizzle-padded smem
    {
        int lr = t >> 2, g = t & 3;
        const float4* src = (const float4*)(Q + (bh + n0 + lr) * DH) + g * 4;
        float4* dst = (float4*)(Qs + lr * SM_STRIDE) + g * 4;
        #pragma unroll
        for (int j = 0; j < 4; j++) dst[j] = src[j];
    }

    int r = t >> 2, sub = t & 3;
    int lane = t & 31;
    float o_[16];
    #pragma unroll
    for (int i = 0; i < 16; i++) o_[i] = 0.f;
    float m = -1e30f, l = 0.f;

    int tstart = (wi == 0) ? 8 : 0;
    int tend = qb + 8;

    for (int tt = tstart; tt <= tend; tt++) {
        int kglob = wi * WW - WW + tt * 64;   // >= 0 for processed tiles
        __syncthreads();                      // protect Ks/Vs (also covers Q load, iter 1)
        {
            int lr = t >> 2, g = t & 3;
            const float4* ks = (const float4*)(K + (bh + kglob + lr) * DH) + g * 4;
            const float4* vs = (const float4*)(V + (bh + kglob + lr) * DH) + g * 4;
            float4* kd = (float4*)(Ks + lr * SM_STRIDE) + g * 4;
            float4* vd = (float4*)(Vs + lr * SM_STRIDE) + g * 4;
            #pragma unroll
            for (int j = 0; j < 4; j++) { kd[j] = ks[j]; vd[j] = vs[j]; }
        }
        __syncthreads();

        // scores: s[j] for key kj = j*4 + sub
        float s[16];
        #pragma unroll
        for (int j = 0; j < 16; j++) s[j] = 0.f;
        #pragma unroll
        for (int d4 = 0; d4 < 16; d4++) {
            float4 qv = *((const float4*)(Qs + r * SM_STRIDE) + d4);
            #pragma unroll
            for (int j = 0; j < 16; j++) {
                float4 kv = *((const float4*)(Ks + (j * 4 + sub) * SM_STRIDE) + d4);
                s[j] += qv.x * kv.x + qv.y * kv.y + qv.z * kv.z + qv.w * kv.w;
            }
        }

        // diagonal masking
        if (tt == tend) {
            #pragma unroll
            for (int j = 0; j < 16; j++)
                if (j * 4 + sub > r) s[j] = -1e30f;
        }

        // online softmax (row shared by 4 threads of a quad)
        float mt = -1e30f;
        #pragma unroll
        for (int j = 0; j < 16; j++) mt = fmaxf(mt, s[j]);
        mt = fmaxf(mt, __shfl_xor_sync(0xffffffffu, mt, 1));
        mt = fmaxf(mt, __shfl_xor_sync(0xffffffffu, mt, 2));
        float mnew = fmaxf(m, mt);
        float corr = __expf(m - mnew);
        l *= corr;
        #pragma unroll
        for (int i = 0; i < 16; i++) o_[i] *= corr;
        float p[16];
        #pragma unroll
        for (int j = 0; j < 16; j++) {
            float pv = __expf(s[j] - mnew);
            if (s[j] <= -1e29f) pv = 0.f;
            p[j] = pv;
            l += pv;
        }
        m = mnew;

        // o accumulation with quad shuffle exchange of p
        #pragma unroll
        for (int j = 0; j < 16; j++) {
            #pragma unroll
            for (int s2 = 0; s2 < 4; s2++) {
                float pk = __shfl_sync(0xffffffffu, p[j], (lane & ~3) | s2);
                int kk = j * 4 + s2;
                const float* vrow = Vs + kk * SM_STRIDE;
                #pragma unroll
                for (int d4 = 0; d4 < 4; d4++) {
                    float4 vv = *((const float4*)(vrow + d4 * 16 + sub * 4));
                    o_[d4 * 4 + 0] += pk * vv.x;
                    o_[d4 * 4 + 1] += pk * vv.y;
                    o_[d4 * 4 + 2] += pk * vv.z;
                    o_[d4 * 4 + 3] += pk * vv.w;
                }
            }
        }
    }

    // finalize: row denominator across quad
    float lr_ = l;
    lr_ += __shfl_xor_sync(0xffffffffu, lr_, 1);
    lr_ += __shfl_xor_sync(0xffffffffu, lr_, 2);
    float linv = 1.f / lr_;

    int n = n0 + r;
    float* orow = O + ((size_t)(b * NN + n) * DIMD + h * DH);
    #pragma unroll
    for (int d4 = 0; d4 < 4; d4++) {
        float4 vv;
        vv.x = o_[d4 * 4 + 0] * linv;
        vv.y = o_[d4 * 4 + 1] * linv;
        vv.z = o_[d4 * 4 + 2] * linv;
        vv.w = o_[d4 * 4 + 3] * linv;
        *((float4*)(orow + d4 * 16 + sub * 4)) = vv;
    }
}

// ------------------------------ SGEMM ------------------------------
// C[M,N] = A[M,K] (lda) @ B[K,N] (+ R residual). 128x128x8 tile, 8x8/thread.
template<bool RES>
__global__ __launch_bounds__(256) void sgemm_kernel(
    const float* __restrict__ A, int lda,
    const float* __restrict__ B, const float* __restrict__ R,
    float* __restrict__ C, int M, int N, int K)
{
    __shared__ float As[8][128];
    __shared__ float Bs[8][128];
    int t = threadIdx.x;
    int rowBase = blockIdx.y * 128, colBase = blockIdx.x * 128;
    int tx = t & 15, ty = t >> 4;
    int arow = t >> 1, ak = (t & 1) * 4;
    int brow = t >> 5, bcol = (t & 31) * 4;
    bool ncheck = (colBase + 128 > N);

    float acc[8][8];
    #pragma unroll
    for (int i = 0; i < 8; i++)
        #pragma unroll
        for (int j = 0; j < 8; j++) acc[i][j] = 0.f;

    for (int k0 = 0; k0 < K; k0 += 8) {
        // A tile (transposed into As)
        const float* Ap = A + (size_t)(rowBase + arow) * lda + k0 + ak;
        float4 av;
        if (k0 + 8 <= K) {
            av = *(const float4*)Ap;
        } else {
            av.x = (k0 + ak + 0 < K) ? Ap[0] : 0.f;
            av.y = (k0 + ak + 1 < K) ? Ap[1] : 0.f;
            av.z = (k0 + ak + 2 < K) ? Ap[2] : 0.f;
            av.w = (k0 + ak + 3 < K) ? Ap[3] : 0.f;
        }
        As[ak + 0][arow] = av.x; As[ak + 1][arow] = av.y;
        As[ak + 2][arow] = av.z; As[ak + 3][arow] = av.w;

        // B tile
        const float* Bp = B + (size_t)(k0 + brow) * N + colBase + bcol;
        bool kok = (k0 + brow < K);
        float4 bv;
        if (!ncheck && kok) {
            bv = *(const float4*)Bp;
        } else {
            bv.x = (kok && colBase + bcol + 0 < N) ? Bp[0] : 0.f;
            bv.y = (kok && colBase + bcol + 1 < N) ? Bp[1] : 0.f;
            bv.z = (kok && colBase + bcol + 2 < N) ? Bp[2] : 0.f;
            bv.w = (kok && colBase + bcol + 3 < N) ? Bp[3] : 0.f;
        }
        *(float4*)&Bs[brow][bcol] = bv;
        __syncthreads();

        #pragma unroll
        for (int kk = 0; kk < 8; kk++) {
            float4 a0 = *(const float4*)&As[kk][ty * 8];
            float4 a1 = *(const float4*)&As[kk][ty * 8 + 4];
            float4 b0 = *(const float4*)&Bs[kk][tx * 8];
            float4 b1 = *(const float4*)&Bs[kk][tx * 8 + 4];
            float a[8] = {a0.x, a0.y, a0.z, a0.w, a1.x, a1.y, a1.z, a1.w};
            float bb[8] = {b0.x, b0.y, b0.z, b0.w, b1.x, b1.y, b1.z, b1.w};
            #pragma unroll
            for (int i = 0; i < 8; i++)
                #pragma unroll
                for (int j = 0; j < 8; j++)
                    acc[i][j] += a[i] * bb[j];
        }
        __syncthreads();
    }

    // epilogue
    #pragma unroll
    for (int i = 0; i < 8; i++) {
        int grow = rowBase + ty * 8 + i;
        float* Cp = C + (size_t)grow * N + colBase + tx * 8;
        const float* Rp = R + (size_t)grow * N + colBase + tx * 8;  // only if RES
        if (!ncheck) {
            float4 c0 = {acc[i][0], acc[i][1], acc[i][2], acc[i][3]};
            float4 c1 = {acc[i][4], acc[i][5], acc[i][6], acc[i][7]};
            if (RES) {
                float4 r0 = ((const float4*)Rp)[0];
                float4 r1 = ((const float4*)Rp)[1];
                c0.x += r0.x; c0.y += r0.y; c0.z += r0.z; c0.w += r0.w;
                c1.x += r1.x; c1.y += r1.y; c1.z += r1.z; c1.w += r1.w;
            }
            ((float4*)Cp)[0] = c0;
            ((float4*)Cp)[1] = c1;
        } else {
            #pragma unroll
            for (int j = 0; j < 8; j++) {
                int gc = colBase + tx * 8 + j;
                if (gc < N) {
                    float v = acc[i][j];
                    if (RES) v += Rp[j];
                    Cp[j] = v;
                }
            }
        }
    }
}

// ------------------------------- GEGLU -------------------------------
__global__ __launch_bounds__(256) void geglu_kernel(
    const float* __restrict__ U, float* __restrict__ G)
{
    int idx = blockIdx.x * blockDim.x + threadIdx.x;
    const int total = ROWS * GGW;
    if (idx >= total) return;
    int row = idx / GGW;
    int c = idx - row * GGW;
    float val = 0.f;
    if (c < INNER) {
        float a = U[(size_t)row * FF1N + c];
        float g = U[(size_t)row * FF1N + INNER + c];
        float ge = 0.5f * g * (1.f + erff(g * 0.70710678118654752f));
        val = a * ge;
    }
    G[idx] = val;
}

// ------------------------------ launch ------------------------------
extern "C" void kernel_launch(void* const* d_in, const int* in_sizes, int n_in,
                              void* d_out, int out_size)
{
    const float* x     = (const float*)d_in[0];
    const float* ln1_w = (const float*)d_in[1];
    const float* ln1_b = (const float*)d_in[2];
    const float* w_qkv = (const float*)d_in[3];
    const float* w_out = (const float*)d_in[4];
    const float* ln2_w = (const float*)d_in[5];
    const float* w_ff1 = (const float*)d_in[6];
    const float* w_ff2 = (const float*)d_in[7];
    float* out = (float*)d_out;

    float *p_h, *p_qkv, *p_q, *p_k, *p_v, *p_attn, *p_x1, *p_u, *p_gg;
    cudaGetSymbolAddress((void**)&p_h,    g_h);
    cudaGetSymbolAddress((void**)&p_qkv,  g_qkv);
    cudaGetSymbolAddress((void**)&p_q,    g_q);
    cudaGetSymbolAddress((void**)&p_k,    g_k);
    cudaGetSymbolAddress((void**)&p_v,    g_v);
    cudaGetSymbolAddress((void**)&p_attn, g_attn);
    cudaGetSymbolAddress((void**)&p_x1,   g_x1);
    cudaGetSymbolAddress((void**)&p_u,    g_u);
    cudaGetSymbolAddress((void**)&p_gg,   g_gg);

    const int ATTN_SMEM = 3 * 64 * SM_STRIDE * (int)sizeof(float);  // 52224
    cudaFuncSetAttribute(attn_kernel, cudaFuncAttributeMaxDynamicSharedMemorySize, ATTN_SMEM);

    // 1. LN1
    ln_kernel<<<ROWS, 256>>>(x, ln1_w, ln1_b, p_h);
    // 2. QKV = h @ w_qkv
    sgemm_kernel<false><<<dim3(QKVN / 128, ROWS / 128), 256>>>(
        p_h, DIMD, w_qkv, nullptr, p_qkv, ROWS, QKVN, DIMD);
    // 3. rotary + head split
    rope_kernel<<<ROWS, 512>>>(p_qkv, p_q, p_k, p_v);
    // 4. windowed attention
    attn_kernel<<<BB * HEADS * NW * (WW / 64), 256, ATTN_SMEM>>>(p_q, p_k, p_v, p_attn);
    // 5. out proj + residual
    sgemm_kernel<true><<<dim3(DIMD / 128, ROWS / 128), 256>>>(
        p_attn, DIMD, w_out, x, p_x1, ROWS, DIMD, DIMD);
    // 6. LN2 (gamma only)
    ln_kernel<<<ROWS, 256>>>(p_x1, ln2_w, nullptr, p_h);
    // 7. FF1
    sgemm_kernel<false><<<dim3((FF1N + 127) / 128, ROWS / 128), 256>>>(
        p_h, DIMD, w_ff1, nullptr, p_u, ROWS, FF1N, DIMD);
    // 8. GEGLU (into padded GGW buffer, zeros in pad cols)
    {
        int total = ROWS * GGW;
        geglu_kernel<<<(total + 255) / 256, 256>>>(p_u, p_gg);
    }
    // 9. FF2 + residual -> out
    sgemm_kernel<true><<<dim3(DIMD / 128, ROWS / 128), 256>>>(
        p_gg, GGW, w_ff2, p_x1, out, ROWS, DIMD, INNER);
}

// round 2
// speedup vs baseline: 1.9370x; 1.9370x over previous
#include <cuda_runtime.h>
#include <math.h>

#define BB 2
#define NN 4096
#define DIMD 1024
#define HEADS 16
#define DH 64
#define WW 512
#define NW (NN/WW)          // 8
#define INNER 2730
#define GGW 2736            // padded INNER -> multiple of 16 for GEMM k-stages
#define ROWS (BB*NN)        // 8192
#define QKVN (3*HEADS*DH)   // 3072
#define FF1N (2*INNER)      // 5460

// ------------------- scratch (device globals; no allocation) -------------------
__device__ float g_h   [ROWS*DIMD];
__device__ float g_qkv [ROWS*QKVN];
__device__ float g_q   [BB*HEADS*NN*DH];
__device__ float g_k   [BB*HEADS*NN*DH];
__device__ float g_v   [BB*HEADS*NN*DH];
__device__ float g_attn[ROWS*DIMD];
__device__ float g_x1  [ROWS*DIMD];
__device__ float g_u   [ROWS*FF1N];
__device__ float g_gg  [ROWS*GGW];

// ------------------------------- LayerNorm -------------------------------
__global__ __launch_bounds__(256) void ln_kernel(
    const float* __restrict__ X, const float* __restrict__ w,
    const float* __restrict__ b, float* __restrict__ Y)
{
    __shared__ float sa[8], sb[8];
    int row = blockIdx.x;
    int t = threadIdx.x;
    const float4* xr = (const float4*)(X + (size_t)row * DIMD);
    float4 xv = xr[t];
    float s  = xv.x + xv.y + xv.z + xv.w;
    float sq = xv.x*xv.x + xv.y*xv.y + xv.z*xv.z + xv.w*xv.w;

    int lane = t & 31, wrp = t >> 5;
    #pragma unroll
    for (int o = 16; o; o >>= 1) {
        s  += __shfl_xor_sync(0xffffffffu, s,  o);
        sq += __shfl_xor_sync(0xffffffffu, sq, o);
    }
    if (lane == 0) { sa[wrp] = s; sb[wrp] = sq; }
    __syncthreads();
    if (wrp == 0) {
        s  = (lane < 8) ? sa[lane] : 0.f;
        sq = (lane < 8) ? sb[lane] : 0.f;
        #pragma unroll
        for (int o = 4; o; o >>= 1) {
            s  += __shfl_xor_sync(0xffffffffu, s,  o);
            sq += __shfl_xor_sync(0xffffffffu, sq, o);
        }
        if (lane == 0) { sa[0] = s; sb[0] = sq; }
    }
    __syncthreads();
    float mean = sa[0] * (1.f / DIMD);
    float var  = sb[0] * (1.f / DIMD) - mean * mean;
    float inv  = rsqrtf(var + 1e-5f);

    float4 wv = ((const float4*)w)[t];
    float4 out;
    out.x = (xv.x - mean) * inv * wv.x;
    out.y = (xv.y - mean) * inv * wv.y;
    out.z = (xv.z - mean) * inv * wv.z;
    out.w = (xv.w - mean) * inv * wv.w;
    if (b) {
        float4 bv = ((const float4*)b)[t];
        out.x += bv.x; out.y += bv.y; out.z += bv.z; out.w += bv.w;
    }
    ((float4*)(Y + (size_t)row * DIMD))[t] = out;
}

// ----------------------- rotary + head split (+q scale) -----------------------
__global__ __launch_bounds__(512) void rope_kernel(
    const float* __restrict__ QKV, float* __restrict__ Q,
    float* __restrict__ K, float* __restrict__ V)
{
    int row = blockIdx.x;
    int b = row >> 12, n = row & (NN - 1);
    int t = threadIdx.x;
    const float* base = QKV + (size_t)row * QKVN;

    int h = t >> 5, dj = t & 31;
    float inv = powf(10000.f, -(float)dj * (1.f / 32.f));
    float f = (float)n * inv;
    float sn, cs; sincosf(f, &sn, &cs);

    size_t o = ((size_t)(b * HEADS + h) * NN + n) * DH;
    float x1 = base[h * DH + dj];
    float x2 = base[h * DH + dj + 32];
    Q[o + dj]      = (x1 * cs - x2 * sn) * 0.125f;
    Q[o + dj + 32] = (x2 * cs + x1 * sn) * 0.125f;
    x1 = base[DIMD + h * DH + dj];
    x2 = base[DIMD + h * DH + dj + 32];
    K[o + dj]      = x1 * cs - x2 * sn;
    K[o + dj + 32] = x2 * cs + x1 * sn;
    int c0 = t, c1 = t + 512;
    V[((size_t)(b * HEADS + (c0 >> 6)) * NN + n) * DH + (c0 & 63)] = base[2 * DIMD + c0];
    V[((size_t)(b * HEADS + (c1 >> 6)) * NN + n) * DH + (c1 & 63)] = base[2 * DIMD + c1];
}

// --------------------------- windowed attention (fp32) ---------------------------
#define SM_STRIDE 68
__global__ __launch_bounds__(256) void attn_kernel(
    const float* __restrict__ Q, const float* __restrict__ K,
    const float* __restrict__ V, float* __restrict__ O)
{
    extern __shared__ float sm[];
    float* Qs = sm;
    float* Ks = sm + 64 * SM_STRIDE;
    float* Vs = sm + 2 * 64 * SM_STRIDE;

    int idx = blockIdx.x;
    int qb = idx & 7;
    int wi = (idx >> 3) & 7;
    int h  = (idx >> 6) & 15;
    int b  = idx >> 10;
    int t  = threadIdx.x;

    const size_t bh = ((size_t)b * HEADS + h) * NN;
    int n0 = wi * WW + qb * 64;

    {
        int lr = t >> 2, g = t & 3;
        const float4* src = (const float4*)(Q + (bh + n0 + lr) * DH) + g * 4;
        float4* dst = (float4*)(Qs + lr * SM_STRIDE) + g * 4;
        #pragma unroll
        for (int j = 0; j < 4; j++) dst[j] = src[j];
    }

    int r = t >> 2, sub = t & 3;
    int lane = t & 31;
    float o_[16];
    #pragma unroll
    for (int i = 0; i < 16; i++) o_[i] = 0.f;
    float m = -1e30f, l = 0.f;

    int tstart = (wi == 0) ? 8 : 0;
    int tend = qb + 8;

    for (int tt = tstart; tt <= tend; tt++) {
        int kglob = wi * WW - WW + tt * 64;
        __syncthreads();
        {
            int lr = t >> 2, g = t & 3;
            const float4* ks = (const float4*)(K + (bh + kglob + lr) * DH) + g * 4;
            const float4* vs = (const float4*)(V + (bh + kglob + lr) * DH) + g * 4;
            float4* kd = (float4*)(Ks + lr * SM_STRIDE) + g * 4;
            float4* vd = (float4*)(Vs + lr * SM_STRIDE) + g * 4;
            #pragma unroll
            for (int j = 0; j < 4; j++) { kd[j] = ks[j]; vd[j] = vs[j]; }
        }
        __syncthreads();

        float s[16];
        #pragma unroll
        for (int j = 0; j < 16; j++) s[j] = 0.f;
        #pragma unroll
        for (int d4 = 0; d4 < 16; d4++) {
            float4 qv = *((const float4*)(Qs + r * SM_STRIDE) + d4);
            #pragma unroll
            for (int j = 0; j < 16; j++) {
                float4 kv = *((const float4*)(Ks + (j * 4 + sub) * SM_STRIDE) + d4);
                s[j] += qv.x * kv.x + qv.y * kv.y + qv.z * kv.z + qv.w * kv.w;
            }
        }

        if (tt == tend) {
            #pragma unroll
            for (int j = 0; j < 16; j++)
                if (j * 4 + sub > r) s[j] = -1e30f;
        }

        float mt = -1e30f;
        #pragma unroll
        for (int j = 0; j < 16; j++) mt = fmaxf(mt, s[j]);
        mt = fmaxf(mt, __shfl_xor_sync(0xffffffffu, mt, 1));
        mt = fmaxf(mt, __shfl_xor_sync(0xffffffffu, mt, 2));
        float mnew = fmaxf(m, mt);
        float corr = __expf(m - mnew);
        l *= corr;
        #pragma unroll
        for (int i = 0; i < 16; i++) o_[i] *= corr;
        float p[16];
        #pragma unroll
        for (int j = 0; j < 16; j++) {
            float pv = __expf(s[j] - mnew);
            if (s[j] <= -1e29f) pv = 0.f;
            p[j] = pv;
            l += pv;
        }
        m = mnew;

        #pragma unroll
        for (int j = 0; j < 16; j++) {
            #pragma unroll
            for (int s2 = 0; s2 < 4; s2++) {
                float pk = __shfl_sync(0xffffffffu, p[j], (lane & ~3) | s2);
                int kk = j * 4 + s2;
                const float* vrow = Vs + kk * SM_STRIDE;
                #pragma unroll
                for (int d4 = 0; d4 < 4; d4++) {
                    float4 vv = *((const float4*)(vrow + d4 * 16 + sub * 4));
                    o_[d4 * 4 + 0] += pk * vv.x;
                    o_[d4 * 4 + 1] += pk * vv.y;
                    o_[d4 * 4 + 2] += pk * vv.z;
                    o_[d4 * 4 + 3] += pk * vv.w;
                }
            }
        }
    }

    float lr_ = l;
    lr_ += __shfl_xor_sync(0xffffffffu, lr_, 1);
    lr_ += __shfl_xor_sync(0xffffffffu, lr_, 2);
    float linv = 1.f / lr_;

    int n = n0 + r;
    float* orow = O + ((size_t)(b * NN + n) * DIMD + h * DH);
    #pragma unroll
    for (int d4 = 0; d4 < 4; d4++) {
        float4 vv;
        vv.x = o_[d4 * 4 + 0] * linv;
        vv.y = o_[d4 * 4 + 1] * linv;
        vv.z = o_[d4 * 4 + 2] * linv;
        vv.w = o_[d4 * 4 + 3] * linv;
        *((float4*)(orow + d4 * 16 + sub * 4)) = vv;
    }
}

// ------------------------------ TF32 tensor-core GEMM ------------------------------
// C[M,N] = A[M,K](lda) @ B[K,N] (+R). CTA 128x128, 8 warps (2x4), warp 64x32.
// k-stage 16, double-buffered smem. N must be even. M multiple of 128.
__device__ __forceinline__ float tf32r(float x) {
    unsigned u; asm("cvt.rna.tf32.f32 %0, %1;" : "=r"(u) : "f"(x));
    return __uint_as_float(u);
}

#define PA 20
#define PB 136

template<bool RES>
__global__ __launch_bounds__(256) void tf32_gemm(
    const float* __restrict__ A, int lda,
    const float* __restrict__ B, const float* __restrict__ R,
    float* __restrict__ C, int N, int Kb, int Kpad)
{
    __shared__ float As[2][128][PA];   // [buf][m][k]
    __shared__ float Bs[2][16][PB];    // [buf][k][n]
    const int t = threadIdx.x;
    const int rowBase = blockIdx.y * 128, colBase = blockIdx.x * 128;
    const int warp = t >> 5, lane = t & 31;
    const int wm = warp >> 2, wn = warp & 3;
    const int q = lane & 3, g = lane >> 2;
    const bool ntail = (colBase + 128 > N);

    float acc[4][4][4];
    #pragma unroll
    for (int i = 0; i < 4; i++)
        #pragma unroll
        for (int j = 0; j < 4; j++)
            #pragma unroll
            for (int rr = 0; rr < 4; rr++) acc[i][j][rr] = 0.f;

    const int am0 = t >> 2;       // A loader: m (and m+64), kg = t&3
    const int akg = t & 3;
    const int bk0 = t >> 5;       // B loader: krow (and +8), ng = t&31
    const int bng = t & 31;

    float4 ar[2], br[2];

    // ---- fetch global -> regs for k-stage k0 ----
    #define FETCH(k0)                                                          \
    {                                                                          \
        _Pragma("unroll")                                                      \
        for (int i = 0; i < 2; i++) {                                          \
            int m = am0 + i * 64;                                              \
            ar[i] = *(const float4*)(A + (size_t)(rowBase + m) * lda + (k0) + akg * 4); \
        }                                                                      \
        _Pragma("unroll")                                                      \
        for (int i = 0; i < 2; i++) {                                          \
            int kidx = (k0) + bk0 + i * 8;                                     \
            const float* p = B + (size_t)kidx * N + colBase + bng * 4;         \
            if (kidx < Kb && !ntail) {                                         \
                br[i] = *(const float4*)p;                                     \
            } else {                                                           \
                int c0 = colBase + bng * 4;                                    \
                br[i].x = (kidx < Kb && c0 + 0 < N) ? p[0] : 0.f;              \
                br[i].y = (kidx < Kb && c0 + 1 < N) ? p[1] : 0.f;              \
                br[i].z = (kidx < Kb && c0 + 2 < N) ? p[2] : 0.f;              \
                br[i].w = (kidx < Kb && c0 + 3 < N) ? p[3] : 0.f;              \
            }                                                                  \
        }                                                                      \
    }

    // ---- regs -> smem (with tf32 rounding) ----
    #define STORE(bufi)                                                        \
    {                                                                          \
        _Pragma("unroll")                                                      \
        for (int i = 0; i < 2; i++) {                                          \
            int m = am0 + i * 64;                                              \
            As[bufi][m][akg * 4 + 0] = tf32r(ar[i].x);                         \
            As[bufi][m][akg * 4 + 1] = tf32r(ar[i].y);                         \
            As[bufi][m][akg * 4 + 2] = tf32r(ar[i].z);                         \
            As[bufi][m][akg * 4 + 3] = tf32r(ar[i].w);                         \
        }                                                                      \
        _Pragma("unroll")                                                      \
        for (int i = 0; i < 2; i++) {                                          \
            int kr = bk0 + i * 8;                                              \
            float4 v = br[i];                                                  \
            v.x = tf32r(v.x); v.y = tf32r(v.y);                                \
            v.z = tf32r(v.z); v.w = tf32r(v.w);                                \
            *(float4*)&Bs[bufi][kr][bng * 4] = v;                              \
        }                                                                      \
    }

    // ---- compute one k16 stage ----
    #define COMPUTE(bufi)                                                      \
    {                                                                          \
        _Pragma("unroll")                                                      \
        for (int kk = 0; kk < 16; kk += 8) {                                   \
            unsigned a[4][4], b[4][2];                                         \
            _Pragma("unroll")                                                  \
            for (int mf = 0; mf < 4; mf++) {                                   \
                int m = wm * 64 + mf * 16 + g;                                 \
                a[mf][0] = __float_as_uint(As[bufi][m    ][kk + q]);           \
                a[mf][1] = __float_as_uint(As[bufi][m + 8][kk + q]);           \
                a[mf][2] = __float_as_uint(As[bufi][m    ][kk + q + 4]);       \
                a[mf][3] = __float_as_uint(As[bufi][m + 8][kk + q + 4]);       \
            }                                                                  \
            _Pragma("unroll")                                                  \
            for (int nf = 0; nf < 4; nf++) {                                   \
                int n = wn * 32 + nf * 8 + g;                                  \
                b[nf][0] = __float_as_uint(Bs[bufi][kk + q    ][n]);           \
                b[nf][1] = __float_as_uint(Bs[bufi][kk + q + 4][n]);           \
            }                                                                  \
            _Pragma("unroll")                                                  \
            for (int mf = 0; mf < 4; mf++)                                     \
                _Pragma("unroll")                                              \
                for (int nf = 0; nf < 4; nf++)                                 \
                    asm volatile(                                              \
                        "mma.sync.aligned.m16n8k8.row.col.f32.tf32.tf32.f32 "  \
                        "{%0,%1,%2,%3}, {%4,%5,%6,%7}, {%8,%9}, {%0,%1,%2,%3};\n" \
                        : "+f"(acc[mf][nf][0]), "+f"(acc[mf][nf][1]),          \
                          "+f"(acc[mf][nf][2]), "+f"(acc[mf][nf][3])           \
                        : "r"(a[mf][0]), "r"(a[mf][1]),                        \
                          "r"(a[mf][2]), "r"(a[mf][3]),                        \
                          "r"(b[nf][0]), "r"(b[nf][1]));                       \
        }                                                                      \
    }

    FETCH(0);
    STORE(0);
    __syncthreads();
    int buf = 0;
    for (int k0 = 16; k0 < Kpad; k0 += 16) {
        FETCH(k0);
        COMPUTE(buf);
        STORE(buf ^ 1);
        __syncthreads();
        buf ^= 1;
    }
    COMPUTE(buf);

    // epilogue (N even => float2 stores fully in/out)
    #pragma unroll
    for (int mf = 0; mf < 4; mf++) {
        #pragma unroll
        for (int i = 0; i < 2; i++) {
            int grow = rowBase + wm * 64 + mf * 16 + g + i * 8;
            #pragma unroll
            for (int nf = 0; nf < 4; nf++) {
                int gcol = colBase + wn * 32 + nf * 8 + q * 2;
                if (gcol < N) {
                    float v0 = acc[mf][nf][i * 2 + 0];
                    float v1 = acc[mf][nf][i * 2 + 1];
                    if (RES) {
                        const float* Rp = R + (size_t)grow * N + gcol;
                        v0 += Rp[0]; v1 += Rp[1];
                    }
                    *(float2*)(C + (size_t)grow * N + gcol) = make_float2(v0, v1);
                }
            }
        }
    }
    #undef FETCH
    #undef STORE
    #undef COMPUTE
}

// ------------------------------- GEGLU -------------------------------
__global__ __launch_bounds__(256) void geglu_kernel(
    const float* __restrict__ U, float* __restrict__ G)
{
    int idx = blockIdx.x * blockDim.x + threadIdx.x;
    const int total = ROWS * GGW;
    if (idx >= total) return;
    int row = idx / GGW;
    int c = idx - row * GGW;
    float val = 0.f;
    if (c < INNER) {
        float a = U[(size_t)row * FF1N + c];
        float g = U[(size_t)row * FF1N + INNER + c];
        float ge = 0.5f * g * (1.f + erff(g * 0.70710678118654752f));
        val = a * ge;
    }
    G[idx] = val;
}

// ------------------------------ launch ------------------------------
extern "C" void kernel_launch(void* const* d_in, const int* in_sizes, int n_in,
                              void* d_out, int out_size)
{
    const float* x     = (const float*)d_in[0];
    const float* ln1_w = (const float*)d_in[1];
    const float* ln1_b = (const float*)d_in[2];
    const float* w_qkv = (const float*)d_in[3];
    const float* w_out = (const float*)d_in[4];
    const float* ln2_w = (const float*)d_in[5];
    const float* w_ff1 = (const float*)d_in[6];
    const float* w_ff2 = (const float*)d_in[7];
    float* out = (float*)d_out;

    float *p_h, *p_qkv, *p_q, *p_k, *p_v, *p_attn, *p_x1, *p_u, *p_gg;
    cudaGetSymbolAddress((void**)&p_h,    g_h);
    cudaGetSymbolAddress((void**)&p_qkv,  g_qkv);
    cudaGetSymbolAddress((void**)&p_q,    g_q);
    cudaGetSymbolAddress((void**)&p_k,    g_k);
    cudaGetSymbolAddress((void**)&p_v,    g_v);
    cudaGetSymbolAddress((void**)&p_attn, g_attn);
    cudaGetSymbolAddress((void**)&p_x1,   g_x1);
    cudaGetSymbolAddress((void**)&p_u,    g_u);
    cudaGetSymbolAddress((void**)&p_gg,   g_gg);

    const int ATTN_SMEM = 3 * 64 * SM_STRIDE * (int)sizeof(float);
    cudaFuncSetAttribute(attn_kernel, cudaFuncAttributeMaxDynamicSharedMemorySize, ATTN_SMEM);

    // 1. LN1
    ln_kernel<<<ROWS, 256>>>(x, ln1_w, ln1_b, p_h);
    // 2. QKV = h @ w_qkv     (M=8192, N=3072, K=1024)
    tf32_gemm<false><<<dim3(QKVN / 128, ROWS / 128), 256>>>(
        p_h, DIMD, w_qkv, nullptr, p_qkv, QKVN, DIMD, DIMD);
    // 3. rotary + head split
    rope_kernel<<<ROWS, 512>>>(p_qkv, p_q, p_k, p_v);
    // 4. windowed attention
    attn_kernel<<<BB * HEADS * NW * (WW / 64), 256, ATTN_SMEM>>>(p_q, p_k, p_v, p_attn);
    // 5. out proj + residual (M=8192, N=1024, K=1024)
    tf32_gemm<true><<<dim3(DIMD / 128, ROWS / 128), 256>>>(
        p_attn, DIMD, w_out, x, p_x1, DIMD, DIMD, DIMD);
    // 6. LN2 (gamma only)
    ln_kernel<<<ROWS, 256>>>(p_x1, ln2_w, nullptr, p_h);
    // 7. FF1 (M=8192, N=5460, K=1024)
    tf32_gemm<false><<<dim3((FF1N + 127) / 128, ROWS / 128), 256>>>(
        p_h, DIMD, w_ff1, nullptr, p_u, FF1N, DIMD, DIMD);
    // 8. GEGLU -> padded buffer (zeros in cols [INNER, GGW))
    {
        int total = ROWS * GGW;
        geglu_kernel<<<(total + 255) / 256, 256>>>(p_u, p_gg);
    }
    // 9. FF2 + residual -> out (M=8192, N=1024, K=2730 real / 2736 padded)
    tf32_gemm<true><<<dim3(DIMD / 128, ROWS / 128), 256>>>(
        p_gg, GGW, w_ff2, p_x1, out, DIMD, INNER, GGW);
}

// round 4
// speedup vs baseline: 3.0121x; 1.5551x over previous
#include <cuda_runtime.h>
#include <cuda_fp16.h>
#include <math.h>

#define BB 2
#define NN 4096
#define DIMD 1024
#define HEADS 16
#define DH 64
#define WW 512
#define NW (NN/WW)          // 8
#define INNER 2730
#define GGW2 2752           // INNER padded to multiple of 32 (K-stages)
#define ROWS (BB*NN)        // 8192
#define QKVN (3*HEADS*DH)   // 3072
#define FF1N (2*INNER)      // 5460
#define FF1NP 5504          // padded FF1 N (43*128) -> aligned rows, no B tail

typedef __half h16;

// ------------------- scratch (device globals; no allocation) -------------------
__device__ h16   g_hh  [ROWS*DIMD];       // LN1/LN2 output (fp16 GEMM input)
__device__ float g_qkv [ROWS*QKVN];
__device__ float g_q   [BB*HEADS*NN*DH];
__device__ float g_k   [BB*HEADS*NN*DH];
__device__ float g_v   [BB*HEADS*NN*DH];
__device__ h16   g_attnh[ROWS*DIMD];
__device__ float g_x1  [ROWS*DIMD];
__device__ float g_u   [ROWS*FF1N];
__device__ h16   g_ggh [ROWS*GGW2];
// fp16 weights
__device__ h16   g_wqkv[DIMD*QKVN];
__device__ h16   g_wout[DIMD*DIMD];
__device__ h16   g_wff1[DIMD*FF1NP];      // padded columns [FF1N, FF1NP) = 0
__device__ h16   g_wff2[INNER*DIMD];

// --------------------------- float -> fp16 convert ---------------------------
__global__ __launch_bounds__(256) void f2h_kernel(
    const float* __restrict__ src, h16* __restrict__ dst, int n4)
{
    int i = blockIdx.x * blockDim.x + threadIdx.x;
    if (i >= n4) return;
    float4 v = ((const float4*)src)[i];
    half2* d = (half2*)dst + i * 2;
    d[0] = __floats2half2_rn(v.x, v.y);
    d[1] = __floats2half2_rn(v.z, v.w);
}

// float [rows x FF1N] -> fp16 [rows x FF1NP] zero-padded
__global__ __launch_bounds__(256) void f2h_pad_kernel(
    const float* __restrict__ src, h16* __restrict__ dst)
{
    int idx = blockIdx.x * blockDim.x + threadIdx.x;
    const int total = DIMD * FF1NP;
    if (idx >= total) return;
    int row = idx / FF1NP;
    int col = idx - row * FF1NP;
    float v = (col < FF1N) ? src[(size_t)row * FF1N + col] : 0.f;
    dst[idx] = __float2half_rn(v);
}

// ------------------------------- LayerNorm (fp32 in -> fp16 out) -------------------------------
__global__ __launch_bounds__(256) void ln_kernel(
    const float* __restrict__ X, const float* __restrict__ w,
    const float* __restrict__ b, h16* __restrict__ Y)
{
    __shared__ float sa[8], sb[8];
    int row = blockIdx.x;
    int t = threadIdx.x;
    const float4* xr = (const float4*)(X + (size_t)row * DIMD);
    float4 xv = xr[t];
    float s  = xv.x + xv.y + xv.z + xv.w;
    float sq = xv.x*xv.x + xv.y*xv.y + xv.z*xv.z + xv.w*xv.w;

    int lane = t & 31, wrp = t >> 5;
    #pragma unroll
    for (int o = 16; o; o >>= 1) {
        s  += __shfl_xor_sync(0xffffffffu, s,  o);
        sq += __shfl_xor_sync(0xffffffffu, sq, o);
    }
    if (lane == 0) { sa[wrp] = s; sb[wrp] = sq; }
    __syncthreads();
    if (wrp == 0) {
        s  = (lane < 8) ? sa[lane] : 0.f;
        sq = (lane < 8) ? sb[lane] : 0.f;
        #pragma unroll
        for (int o = 4; o; o >>= 1) {
            s  += __shfl_xor_sync(0xffffffffu, s,  o);
            sq += __shfl_xor_sync(0xffffffffu, sq, o);
        }
        if (lane == 0) { sa[0] = s; sb[0] = sq; }
    }
    __syncthreads();
    float mean = sa[0] * (1.f / DIMD);
    float var  = sb[0] * (1.f / DIMD) - mean * mean;
    float inv  = rsqrtf(var + 1e-5f);

    float4 wv = ((const float4*)w)[t];
    float4 out;
    out.x = (xv.x - mean) * inv * wv.x;
    out.y = (xv.y - mean) * inv * wv.y;
    out.z = (xv.z - mean) * inv * wv.z;
    out.w = (xv.w - mean) * inv * wv.w;
    if (b) {
        float4 bv = ((const float4*)b)[t];
        out.x += bv.x; out.y += bv.y; out.z += bv.z; out.w += bv.w;
    }
    half2* yr = (half2*)(Y + (size_t)row * DIMD);
    yr[2 * t + 0] = __floats2half2_rn(out.x, out.y);
    yr[2 * t + 1] = __floats2half2_rn(out.z, out.w);
}

// ----------------------- rotary + head split (+q scale), fp32 -----------------------
__global__ __launch_bounds__(512) void rope_kernel(
    const float* __restrict__ QKV, float* __restrict__ Q,
    float* __restrict__ K, float* __restrict__ V)
{
    int row = blockIdx.x;
    int b = row >> 12, n = row & (NN - 1);
    int t = threadIdx.x;
    const float* base = QKV + (size_t)row * QKVN;

    int h = t >> 5, dj = t & 31;
    float inv = powf(10000.f, -(float)dj * (1.f / 32.f));
    float f = (float)n * inv;
    float sn, cs; sincosf(f, &sn, &cs);

    size_t o = ((size_t)(b * HEADS + h) * NN + n) * DH;
    float x1 = base[h * DH + dj];
    float x2 = base[h * DH + dj + 32];
    Q[o + dj]      = (x1 * cs - x2 * sn) * 0.125f;
    Q[o + dj + 32] = (x2 * cs + x1 * sn) * 0.125f;
    x1 = base[DIMD + h * DH + dj];
    x2 = base[DIMD + h * DH + dj + 32];
    K[o + dj]      = x1 * cs - x2 * sn;
    K[o + dj + 32] = x2 * cs + x1 * sn;
    int c0 = t, c1 = t + 512;
    V[((size_t)(b * HEADS + (c0 >> 6)) * NN + n) * DH + (c0 & 63)] = base[2 * DIMD + c0];
    V[((size_t)(b * HEADS + (c1 >> 6)) * NN + n) * DH + (c1 & 63)] = base[2 * DIMD + c1];
}

// --------------------------- windowed attention (fp32, fp16 out) ---------------------------
#define SM_STRIDE 68
__global__ __launch_bounds__(256) void attn_kernel(
    const float* __restrict__ Q, const float* __restrict__ K,
    const float* __restrict__ V, h16* __restrict__ O)
{
    extern __shared__ float sm[];
    float* Qs = sm;
    float* Ks = sm + 64 * SM_STRIDE;
    float* Vs = sm + 2 * 64 * SM_STRIDE;

    int idx = blockIdx.x;
    int qb = idx & 7;
    int wi = (idx >> 3) & 7;
    int h  = (idx >> 6) & 15;
    int b  = idx >> 10;
    int t  = threadIdx.x;

    const size_t bh = ((size_t)b * HEADS + h) * NN;
    int n0 = wi * WW + qb * 64;

    {
        int lr = t >> 2, g = t & 3;
        const float4* src = (const float4*)(Q + (bh + n0 + lr) * DH) + g * 4;
        float4* dst = (float4*)(Qs + lr * SM_STRIDE) + g * 4;
        #pragma unroll
        for (int j = 0; j < 4; j++) dst[j] = src[j];
    }

    int r = t >> 2, sub = t & 3;
    int lane = t & 31;
    float o_[16];
    #pragma unroll
    for (int i = 0; i < 16; i++) o_[i] = 0.f;
    float m = -1e30f, l = 0.f;

    int tstart = (wi == 0) ? 8 : 0;
    int tend = qb + 8;

    for (int tt = tstart; tt <= tend; tt++) {
        int kglob = wi * WW - WW + tt * 64;
        __syncthreads();
        {
            int lr = t >> 2, g = t & 3;
            const float4* ks = (const float4*)(K + (bh + kglob + lr) * DH) + g * 4;
            const float4* vs = (const float4*)(V + (bh + kglob + lr) * DH) + g * 4;
            float4* kd = (float4*)(Ks + lr * SM_STRIDE) + g * 4;
            float4* vd = (float4*)(Vs + lr * SM_STRIDE) + g * 4;
            #pragma unroll
            for (int j = 0; j < 4; j++) { kd[j] = ks[j]; vd[j] = vs[j]; }
        }
        __syncthreads();

        float s[16];
        #pragma unroll
        for (int j = 0; j < 16; j++) s[j] = 0.f;
        #pragma unroll
        for (int d4 = 0; d4 < 16; d4++) {
            float4 qv = *((const float4*)(Qs + r * SM_STRIDE) + d4);
            #pragma unroll
            for (int j = 0; j < 16; j++) {
                float4 kv = *((const float4*)(Ks + (j * 4 + sub) * SM_STRIDE) + d4);
                s[j] += qv.x * kv.x + qv.y * kv.y + qv.z * kv.z + qv.w * kv.w;
            }
        }

        if (tt == tend) {
            #pragma unroll
            for (int j = 0; j < 16; j++)
                if (j * 4 + sub > r) s[j] = -1e30f;
        }

        float mt = -1e30f;
        #pragma unroll
        for (int j = 0; j < 16; j++) mt = fmaxf(mt, s[j]);
        mt = fmaxf(mt, __shfl_xor_sync(0xffffffffu, mt, 1));
        mt = fmaxf(mt, __shfl_xor_sync(0xffffffffu, mt, 2));
        float mnew = fmaxf(m, mt);
        float corr = __expf(m - mnew);
        l *= corr;
        #pragma unroll
        for (int i = 0; i < 16; i++) o_[i] *= corr;
        float p[16];
        #pragma unroll
        for (int j = 0; j < 16; j++) {
            float pv = __expf(s[j] - mnew);
            if (s[j] <= -1e29f) pv = 0.f;
            p[j] = pv;
            l += pv;
        }
        m = mnew;

        #pragma unroll
        for (int j = 0; j < 16; j++) {
            #pragma unroll
            for (int s2 = 0; s2 < 4; s2++) {
                float pk = __shfl_sync(0xffffffffu, p[j], (lane & ~3) | s2);
                int kk = j * 4 + s2;
                const float* vrow = Vs + kk * SM_STRIDE;
                #pragma unroll
                for (int d4 = 0; d4 < 4; d4++) {
                    float4 vv = *((const float4*)(vrow + d4 * 16 + sub * 4));
                    o_[d4 * 4 + 0] += pk * vv.x;
                    o_[d4 * 4 + 1] += pk * vv.y;
                    o_[d4 * 4 + 2] += pk * vv.z;
                    o_[d4 * 4 + 3] += pk * vv.w;
                }
            }
        }
    }

    float lr_ = l;
    lr_ += __shfl_xor_sync(0xffffffffu, lr_, 1);
    lr_ += __shfl_xor_sync(0xffffffffu, lr_, 2);
    float linv = 1.f / lr_;

    int n = n0 + r;
    h16* orow = O + ((size_t)(b * NN + n) * DIMD + h * DH);
    #pragma unroll
    for (int d4 = 0; d4 < 4; d4++) {
        half2* dst = (half2*)(orow + d4 * 16 + sub * 4);
        dst[0] = __floats2half2_rn(o_[d4 * 4 + 0] * linv, o_[d4 * 4 + 1] * linv);
        dst[1] = __floats2half2_rn(o_[d4 * 4 + 2] * linv, o_[d4 * 4 + 3] * linv);
    }
}

// ------------------------------ FP16 tensor-core GEMM ------------------------------
// C[M,Nc](fp32) = A[M,Kpad](h16, lda) @ B[Kb,ldb](h16) (+R fp32, stride Nc).
// CTA 128x128, 8 warps (2x4) of 64x32. k-stage 32, 3-stage cp.async pipeline.
// Requirements: lda*2 % 16 == 0; ldb*2 % 16 == 0; ldb >= gridDim.x*128 (no B col tail);
// A addressable/padded to Kpad; B rows >= Kb zero-filled via cp-size 0. Nc even.
#define STAGES 3
#define ASTR 40                 // h16 per A smem row (32+8 pad)
#define BSTR 136                // h16 per B smem row (128+8 pad)
#define A_STAGE (128*ASTR)
#define B_STAGE (32*BSTR)
#define GEMM_SMEM (STAGES*(A_STAGE+B_STAGE)*2)

__device__ __forceinline__ unsigned cvta_s(const void* p) {
    return (unsigned)__cvta_generic_to_shared(p);
}

template<bool RES>
__global__ __launch_bounds__(256) void h16_gemm(
    const h16* __restrict__ A, int lda,
    const h16* __restrict__ B, int ldb,
    const float* __restrict__ R, float* __restrict__ C,
    int Nc, int Kb, int Kpad)
{
    extern __shared__ char smem_raw[];
    h16* As = (h16*)smem_raw;
    h16* Bs = (h16*)(smem_raw + (size_t)STAGES * A_STAGE * 2);

    const int t = threadIdx.x;
    const int rowBase = blockIdx.y * 128, colBase = blockIdx.x * 128;
    const int warp = t >> 5, lane = t & 31;
    const int wm = warp >> 2, wn = warp & 3;
    const int q = lane & 3, g = lane >> 2;

    float acc[4][4][4];
    #pragma unroll
    for (int i = 0; i < 4; i++)
        #pragma unroll
        for (int j = 0; j < 4; j++)
            #pragma unroll
            for (int rr = 0; rr < 4; rr++) acc[i][j][rr] = 0.f;

    #define ISSUE(k0, s)                                                        \
    {                                                                           \
        _Pragma("unroll")                                                       \
        for (int i = 0; i < 2; i++) {                                           \
            int c = t + i * 256;                                                \
            int row = c >> 2, cc = c & 3;                                       \
            const h16* src = A + (size_t)(rowBase + row) * lda + (k0) + cc * 8; \
            unsigned dst = cvta_s(As + (s) * A_STAGE + row * ASTR + cc * 8);    \
            asm volatile("cp.async.cg.shared.global [%0], [%1], 16;\n"          \
                         :: "r"(dst), "l"(src));                                \
        }                                                                       \
        _Pragma("unroll")                                                       \
        for (int i = 0; i < 2; i++) {                                           \
            int c = t + i * 256;                                                \
            int row = c >> 4, cc = c & 15;                                      \
            int kidx = (k0) + row;                                              \
            int bytes = (kidx < Kb) ? 16 : 0;                                   \
            const h16* src = B + (size_t)(kidx < Kb ? kidx : 0) * ldb           \
                               + colBase + cc * 8;                              \
            unsigned dst = cvta_s(Bs + (s) * B_STAGE + row * BSTR + cc * 8);    \
            asm volatile("cp.async.cg.shared.global [%0], [%1], 16, %2;\n"      \
                         :: "r"(dst), "l"(src), "r"(bytes));                    \
        }                                                                       \
    }

    #define COMPUTE(s)                                                          \
    {                                                                           \
        _Pragma("unroll")                                                       \
        for (int ks = 0; ks < 32; ks += 16) {                                   \
            unsigned a[4][4], bfr[2][4];                                        \
            _Pragma("unroll")                                                   \
            for (int mf = 0; mf < 4; mf++) {                                    \
                int mrow = wm * 64 + mf * 16 + (lane & 15);                     \
                int colofs = ks + ((lane >> 4) << 3);                           \
                unsigned addr = cvta_s(As + (s) * A_STAGE + mrow * ASTR + colofs); \
                asm volatile(                                                   \
                    "ldmatrix.sync.aligned.m8n8.x4.shared.b16 {%0,%1,%2,%3}, [%4];\n" \
                    : "=r"(a[mf][0]), "=r"(a[mf][1]),                           \
                      "=r"(a[mf][2]), "=r"(a[mf][3]) : "r"(addr));              \
            }                                                                   \
            _Pragma("unroll")                                                   \
            for (int nh = 0; nh < 2; nh++) {                                    \
                int krow = ks + (lane & 15);                                    \
                int col = wn * 32 + nh * 16 + ((lane >> 4) << 3);               \
                unsigned addr = cvta_s(Bs + (s) * B_STAGE + krow * BSTR + col); \
                asm volatile(                                                   \
                    "ldmatrix.sync.aligned.m8n8.x4.trans.shared.b16 {%0,%1,%2,%3}, [%4];\n" \
                    : "=r"(bfr[nh][0]), "=r"(bfr[nh][1]),                       \
                      "=r"(bfr[nh][2]), "=r"(bfr[nh][3]) : "r"(addr));          \
            }                                                                   \
            _Pragma("unroll")                                                   \
            for (int mf = 0; mf < 4; mf++)                                      \
                _Pragma("unroll")                                               \
                for (int nf = 0; nf < 4; nf++)                                  \
                    asm volatile(                                               \
                        "mma.sync.aligned.m16n8k16.row.col.f32.f16.f16.f32 "    \
                        "{%0,%1,%2,%3}, {%4,%5,%6,%7}, {%8,%9}, {%0,%1,%2,%3};\n" \
                        : "+f"(acc[mf][nf][0]), "+f"(acc[mf][nf][1]),           \
                          "+f"(acc[mf][nf][2]), "+f"(acc[mf][nf][3])            \
                        : "r"(a[mf][0]), "r"(a[mf][1]),                         \
                          "r"(a[mf][2]), "r"(a[mf][3]),                         \
                          "r"(bfr[nf >> 1][(nf & 1) * 2 + 0]),                  \
                          "r"(bfr[nf >> 1][(nf & 1) * 2 + 1]));                 \
        }                                                                       \
    }

    const int nstage = Kpad / 32;
    ISSUE(0, 0);
    asm volatile("cp.async.commit_group;\n" ::: "memory");
    ISSUE(32, 1);
    asm volatile("cp.async.commit_group;\n" ::: "memory");

    for (int it = 0; it < nstage; it++) {
        asm volatile("cp.async.wait_group 1;\n" ::: "memory");
        __syncthreads();
        int s = it % 3;
        COMPUTE(s);
        if (it + 2 < nstage) {
            int k0 = (it + 2) * 32;
            int s2 = (it + 2) % 3;
            ISSUE(k0, s2);
        }
        asm volatile("cp.async.commit_group;\n" ::: "memory");
    }

    // epilogue (Nc even => float2 stores)
    #pragma unroll
    for (int mf = 0; mf < 4; mf++) {
        #pragma unroll
        for (int i = 0; i < 2; i++) {
            int grow = rowBase + wm * 64 + mf * 16 + g + i * 8;
            #pragma unroll
            for (int nf = 0; nf < 4; nf++) {
                int gcol = colBase + wn * 32 + nf * 8 + q * 2;
                if (gcol < Nc) {
                    float v0 = acc[mf][nf][i * 2 + 0];
                    float v1 = acc[mf][nf][i * 2 + 1];
                    if (RES) {
                        const float* Rp = R + (size_t)grow * Nc + gcol;
                        v0 += Rp[0]; v1 += Rp[1];
                    }
                    *(float2*)(C + (size_t)grow * Nc + gcol) = make_float2(v0, v1);
                }
            }
        }
    }
    #undef ISSUE
    #undef COMPUTE
}

// ------------------------------- GEGLU (fp32 in -> fp16 out, padded) -------------------------------
__global__ __launch_bounds__(256) void geglu_kernel(
    const float* __restrict__ U, h16* __restrict__ G)
{
    int idx = blockIdx.x * blockDim.x + threadIdx.x;
    const int total = ROWS * GGW2;
    if (idx >= total) return;
    int row = idx / GGW2;
    int c = idx - row * GGW2;
    float val = 0.f;
    if (c < INNER) {
        float a = U[(size_t)row * FF1N + c];
        float g = U[(size_t)row * FF1N + INNER + c];
        float ge = 0.5f * g * (1.f + erff(g * 0.70710678118654752f));
        val = a * ge;
    }
    G[idx] = __float2half_rn(val);
}

// ------------------------------ launch ------------------------------
extern "C" void kernel_launch(void* const* d_in, const int* in_sizes, int n_in,
                              void* d_out, int out_size)
{
    const float* x     = (const float*)d_in[0];
    const float* ln1_w = (const float*)d_in[1];
    const float* ln1_b = (const float*)d_in[2];
    const float* w_qkv = (const float*)d_in[3];
    const float* w_out = (const float*)d_in[4];
    const float* ln2_w = (const float*)d_in[5];
    const float* w_ff1 = (const float*)d_in[6];
    const float* w_ff2 = (const float*)d_in[7];
    float* out = (float*)d_out;

    h16 *p_hh, *p_attnh, *p_ggh, *p_wqkv, *p_wout, *p_wff1, *p_wff2;
    float *p_qkv, *p_q, *p_k, *p_v, *p_x1, *p_u;
    cudaGetSymbolAddress((void**)&p_hh,    g_hh);
    cudaGetSymbolAddress((void**)&p_qkv,   g_qkv);
    cudaGetSymbolAddress((void**)&p_q,     g_q);
    cudaGetSymbolAddress((void**)&p_k,     g_k);
    cudaGetSymbolAddress((void**)&p_v,     g_v);
    cudaGetSymbolAddress((void**)&p_attnh, g_attnh);
    cudaGetSymbolAddress((void**)&p_x1,    g_x1);
    cudaGetSymbolAddress((void**)&p_u,     g_u);
    cudaGetSymbolAddress((void**)&p_ggh,   g_ggh);
    cudaGetSymbolAddress((void**)&p_wqkv,  g_wqkv);
    cudaGetSymbolAddress((void**)&p_wout,  g_wout);
    cudaGetSymbolAddress((void**)&p_wff1,  g_wff1);
    cudaGetSymbolAddress((void**)&p_wff2,  g_wff2);

    const int ATTN_SMEM = 3 * 64 * SM_STRIDE * (int)sizeof(float);
    cudaFuncSetAttribute(attn_kernel, cudaFuncAttributeMaxDynamicSharedMemorySize, ATTN_SMEM);
    cudaFuncSetAttribute(h16_gemm<false>, cudaFuncAttributeMaxDynamicSharedMemorySize, GEMM_SMEM);
    cudaFuncSetAttribute(h16_gemm<true>,  cudaFuncAttributeMaxDynamicSharedMemorySize, GEMM_SMEM);

    // 0. convert weights to fp16 (deterministic; every call)
    {
        int n;
        n = DIMD * QKVN / 4;  f2h_kernel<<<(n + 255) / 256, 256>>>(w_qkv, p_wqkv, n);
        n = DIMD * DIMD / 4;  f2h_kernel<<<(n + 255) / 256, 256>>>(w_out, p_wout, n);
        n = INNER * DIMD / 4; f2h_kernel<<<(n + 255) / 256, 256>>>(w_ff2, p_wff2, n);
        n = DIMD * FF1NP;     f2h_pad_kernel<<<(n + 255) / 256, 256>>>(w_ff1, p_wff1);
    }

    // 1. LN1 -> fp16
    ln_kernel<<<ROWS, 256>>>(x, ln1_w, ln1_b, p_hh);
    // 2. QKV = h @ w_qkv  (M=8192, N=3072, K=1024) -> fp32
    h16_gemm<false><<<dim3(QKVN / 128, ROWS / 128), 256, GEMM_SMEM>>>(
        p_hh, DIMD, p_wqkv, QKVN, nullptr, p_qkv, QKVN, DIMD, DIMD);
    // 3. rotary + head split (fp32)
    rope_kernel<<<ROWS, 512>>>(p_qkv, p_q, p_k, p_v);
    // 4. windowed attention (fp32 compute, fp16 out)
    attn_kernel<<<BB * HEADS * NW * (WW / 64), 256, ATTN_SMEM>>>(p_q, p_k, p_v, p_attnh);
    // 5. out proj + residual (M=8192, N=1024, K=1024)
    h16_gemm<true><<<dim3(DIMD / 128, ROWS / 128), 256, GEMM_SMEM>>>(
        p_attnh, DIMD, p_wout, DIMD, x, p_x1, DIMD, DIMD, DIMD);
    // 6. LN2 (gamma only) -> fp16
    ln_kernel<<<ROWS, 256>>>(p_x1, ln2_w, nullptr, p_hh);
    // 7. FF1 (M=8192, Nc=5460, ldb=5504 padded, K=1024) -> fp32
    h16_gemm<false><<<dim3(FF1NP / 128, ROWS / 128), 256, GEMM_SMEM>>>(
        p_hh, DIMD, p_wff1, FF1NP, nullptr, p_u, FF1N, DIMD, DIMD);
    // 8. GEGLU -> fp16 padded buffer (zeros in cols [INNER, GGW2))
    {
        int total = ROWS * GGW2;
        geglu_kernel<<<(total + 255) / 256, 256>>>(p_u, p_ggh);
    }
    // 9. FF2 + residual -> out (M=8192, N=1024, K=2730 real / 2752 padded)
    h16_gemm<true><<<dim3(DIMD / 128, ROWS / 128), 256, GEMM_SMEM>>>(
        p_ggh, GGW2, p_wff2, DIMD, p_x1, out, DIMD, INNER, GGW2);
}

// round 5
// speedup vs baseline: 8.1304x; 2.6993x over previous
#include <cuda_runtime.h>
#include <cuda_fp16.h>
#include <math.h>

#define BB 2
#define NN 4096
#define DIMD 1024
#define HEADS 16
#define DH 64
#define WW 512
#define NW (NN/WW)          // 8
#define INNER 2730
#define GGW2 2752           // INNER padded to multiple of 32 (K-stages)
#define ROWS (BB*NN)        // 8192
#define QKVN (3*HEADS*DH)   // 3072
#define FF1N (2*INNER)      // 5460
#define FF1NP 5504          // padded FF1 N (43*128)

typedef __half h16;

// ------------------- scratch (device globals; no allocation) -------------------
__device__ h16   g_hh  [ROWS*DIMD];
__device__ float g_qkv [ROWS*QKVN];
__device__ h16   g_qh  [BB*HEADS*NN*DH];
__device__ h16   g_kh  [BB*HEADS*NN*DH];
__device__ h16   g_vh  [BB*HEADS*NN*DH];
__device__ h16   g_attnh[ROWS*DIMD];
__device__ float g_x1  [ROWS*DIMD];
__device__ h16   g_uh  [ROWS*FF1N];
__device__ h16   g_ggh [ROWS*GGW2];
__device__ h16   g_wqkv[DIMD*QKVN];
__device__ h16   g_wout[DIMD*DIMD];
__device__ h16   g_wff1[DIMD*FF1NP];
__device__ h16   g_wff2[INNER*DIMD];

__device__ __forceinline__ unsigned cvta_s(const void* p) {
    return (unsigned)__cvta_generic_to_shared(p);
}
__device__ __forceinline__ float ex2f(float x) {
    float y; asm("ex2.approx.ftz.f32 %0, %1;" : "=f"(y) : "f"(x)); return y;
}
__device__ __forceinline__ void mma16816(float* c, const unsigned* a, unsigned b0, unsigned b1) {
    asm volatile(
        "mma.sync.aligned.m16n8k16.row.col.f32.f16.f16.f32 "
        "{%0,%1,%2,%3}, {%4,%5,%6,%7}, {%8,%9}, {%0,%1,%2,%3};\n"
        : "+f"(c[0]), "+f"(c[1]), "+f"(c[2]), "+f"(c[3])
        : "r"(a[0]), "r"(a[1]), "r"(a[2]), "r"(a[3]), "r"(b0), "r"(b1));
}
__device__ __forceinline__ void ldsm4(unsigned* r, unsigned addr) {
    asm volatile("ldmatrix.sync.aligned.m8n8.x4.shared.b16 {%0,%1,%2,%3}, [%4];\n"
                 : "=r"(r[0]), "=r"(r[1]), "=r"(r[2]), "=r"(r[3]) : "r"(addr));
}
__device__ __forceinline__ void ldsm4t(unsigned* r, unsigned addr) {
    asm volatile("ldmatrix.sync.aligned.m8n8.x4.trans.shared.b16 {%0,%1,%2,%3}, [%4];\n"
                 : "=r"(r[0]), "=r"(r[1]), "=r"(r[2]), "=r"(r[3]) : "r"(addr));
}
__device__ __forceinline__ unsigned packh2(float a, float b) {
    half2 h = __floats2half2_rn(a, b);
    return *(unsigned*)&h;
}

// --------------------------- float -> fp16 convert ---------------------------
__global__ __launch_bounds__(256) void f2h_kernel(
    const float* __restrict__ src, h16* __restrict__ dst, int n4)
{
    int i = blockIdx.x * blockDim.x + threadIdx.x;
    if (i >= n4) return;
    float4 v = ((const float4*)src)[i];
    half2* d = (half2*)dst + i * 2;
    d[0] = __floats2half2_rn(v.x, v.y);
    d[1] = __floats2half2_rn(v.z, v.w);
}

__global__ __launch_bounds__(256) void f2h_pad_kernel(
    const float* __restrict__ src, h16* __restrict__ dst)
{
    int idx = blockIdx.x * blockDim.x + threadIdx.x;
    const int total = DIMD * FF1NP;
    if (idx >= total) return;
    int row = idx / FF1NP;
    int col = idx - row * FF1NP;
    float v = (col < FF1N) ? src[(size_t)row * FF1N + col] : 0.f;
    dst[idx] = __float2half_rn(v);
}

// ------------------------------- LayerNorm -------------------------------
__global__ __launch_bounds__(256) void ln_kernel(
    const float* __restrict__ X, const float* __restrict__ w,
    const float* __restrict__ b, h16* __restrict__ Y)
{
    __shared__ float sa[8], sb[8];
    int row = blockIdx.x;
    int t = threadIdx.x;
    const float4* xr = (const float4*)(X + (size_t)row * DIMD);
    float4 xv = xr[t];
    float s  = xv.x + xv.y + xv.z + xv.w;
    float sq = xv.x*xv.x + xv.y*xv.y + xv.z*xv.z + xv.w*xv.w;

    int lane = t & 31, wrp = t >> 5;
    #pragma unroll
    for (int o = 16; o; o >>= 1) {
        s  += __shfl_xor_sync(0xffffffffu, s,  o);
        sq += __shfl_xor_sync(0xffffffffu, sq, o);
    }
    if (lane == 0) { sa[wrp] = s; sb[wrp] = sq; }
    __syncthreads();
    if (wrp == 0) {
        s  = (lane < 8) ? sa[lane] : 0.f;
        sq = (lane < 8) ? sb[lane] : 0.f;
        #pragma unroll
        for (int o = 4; o; o >>= 1) {
            s  += __shfl_xor_sync(0xffffffffu, s,  o);
            sq += __shfl_xor_sync(0xffffffffu, sq, o);
        }
        if (lane == 0) { sa[0] = s; sb[0] = sq; }
    }
    __syncthreads();
    float mean = sa[0] * (1.f / DIMD);
    float var  = sb[0] * (1.f / DIMD) - mean * mean;
    float inv  = rsqrtf(var + 1e-5f);

    float4 wv = ((const float4*)w)[t];
    float4 out;
    out.x = (xv.x - mean) * inv * wv.x;
    out.y = (xv.y - mean) * inv * wv.y;
    out.z = (xv.z - mean) * inv * wv.z;
    out.w = (xv.w - mean) * inv * wv.w;
    if (b) {
        float4 bv = ((const float4*)b)[t];
        out.x += bv.x; out.y += bv.y; out.z += bv.z; out.w += bv.w;
    }
    half2* yr = (half2*)(Y + (size_t)row * DIMD);
    yr[2 * t + 0] = __floats2half2_rn(out.x, out.y);
    yr[2 * t + 1] = __floats2half2_rn(out.z, out.w);
}

// ----------------------- rotary + head split -> fp16 -----------------------
// Q scaled by DH^-0.5 * log2(e) so attention scores are already in log2 domain.
#define QSCALE (0.125f * 1.44269504088896341f)
__global__ __launch_bounds__(512) void rope_kernel(
    const float* __restrict__ QKV, h16* __restrict__ Q,
    h16* __restrict__ K, h16* __restrict__ V)
{
    int row = blockIdx.x;
    int b = row >> 12, n = row & (NN - 1);
    int t = threadIdx.x;
    const float* base = QKV + (size_t)row * QKVN;

    int h = t >> 5, dj = t & 31;
    float inv = powf(10000.f, -(float)dj * (1.f / 32.f));
    float f = (float)n * inv;
    float sn, cs; sincosf(f, &sn, &cs);

    size_t o = ((size_t)(b * HEADS + h) * NN + n) * DH;
    float x1 = base[h * DH + dj];
    float x2 = base[h * DH + dj + 32];
    Q[o + dj]      = __float2half_rn((x1 * cs - x2 * sn) * QSCALE);
    Q[o + dj + 32] = __float2half_rn((x2 * cs + x1 * sn) * QSCALE);
    x1 = base[DIMD + h * DH + dj];
    x2 = base[DIMD + h * DH + dj + 32];
    K[o + dj]      = __float2half_rn(x1 * cs - x2 * sn);
    K[o + dj + 32] = __float2half_rn(x2 * cs + x1 * sn);
    int c0 = t, c1 = t + 512;
    V[((size_t)(b * HEADS + (c0 >> 6)) * NN + n) * DH + (c0 & 63)] =
        __float2half_rn(base[2 * DIMD + c0]);
    V[((size_t)(b * HEADS + (c1 >> 6)) * NN + n) * DH + (c1 & 63)] =
        __float2half_rn(base[2 * DIMD + c1]);
}

// --------------------------- tensor-core windowed attention ---------------------------
// 128 threads (4 warps); CTA = 64 queries of one (b, h, window, qblock).
// Warp w owns query rows 16w..16w+15. Per 64-key tile: QK^T (m16n8k16),
// online softmax in log2 domain, P@V. K/V double-buffered via cp.async.
#define AT_STR 72   // halves per smem row (64 + 8 pad)
__global__ __launch_bounds__(128) void attn_mma_kernel(
    const h16* __restrict__ Q, const h16* __restrict__ K,
    const h16* __restrict__ V, h16* __restrict__ O)
{
    __shared__ h16 Qs[64 * AT_STR];
    __shared__ h16 Ks[2][64 * AT_STR];
    __shared__ h16 Vs[2][64 * AT_STR];

    int idx = blockIdx.x;
    int qb = idx & 7;
    int wi = (idx >> 3) & 7;
    int h  = (idx >> 6) & 15;
    int b  = idx >> 10;
    int t  = threadIdx.x;
    int warp = t >> 5, lane = t & 31;
    int g = lane >> 2, q = lane & 3;

    const size_t bh = ((size_t)b * HEADS + h) * NN;
    int n0 = wi * WW + qb * 64;
    int tstart = (wi == 0) ? 8 : 0;
    int tend = qb + 8;

    // Q tile load (512 x 16B chunks, 4/thread)
    #pragma unroll
    for (int i = 0; i < 4; i++) {
        int c = t + i * 128;
        int row = c >> 3, cc = c & 7;
        unsigned dst = cvta_s(Qs + row * AT_STR + cc * 8);
        const h16* src = Q + (bh + n0 + row) * DH + cc * 8;
        asm volatile("cp.async.cg.shared.global [%0], [%1], 16;\n" :: "r"(dst), "l"(src));
    }

    #define KV_ISSUE(tt_, buf_)                                                  \
    {                                                                            \
        int kg = wi * WW - WW + (tt_) * 64;                                      \
        _Pragma("unroll")                                                        \
        for (int i = 0; i < 4; i++) {                                            \
            int c = t + i * 128;                                                 \
            int row = c >> 3, cc = c & 7;                                        \
            const h16* ks_ = K + (bh + kg + row) * DH + cc * 8;                  \
            const h16* vs_ = V + (bh + kg + row) * DH + cc * 8;                  \
            unsigned kd = cvta_s(&Ks[buf_][row * AT_STR + cc * 8]);              \
            unsigned vd = cvta_s(&Vs[buf_][row * AT_STR + cc * 8]);              \
            asm volatile("cp.async.cg.shared.global [%0], [%1], 16;\n" :: "r"(kd), "l"(ks_)); \
            asm volatile("cp.async.cg.shared.global [%0], [%1], 16;\n" :: "r"(vd), "l"(vs_)); \
        }                                                                        \
    }

    KV_ISSUE(tstart, 0);
    asm volatile("cp.async.commit_group;\n" ::: "memory");
    if (tstart < tend) { KV_ISSUE(tstart + 1, 1); }
    asm volatile("cp.async.commit_group;\n" ::: "memory");

    float o_[8][4];
    #pragma unroll
    for (int i = 0; i < 8; i++)
        #pragma unroll
        for (int j = 0; j < 4; j++) o_[i][j] = 0.f;
    float m0 = -1e30f, m1 = -1e30f, l0 = 0.f, l1 = 0.f;

    int bsel = 0;
    for (int tt = tstart; tt <= tend; tt++) {
        asm volatile("cp.async.wait_group 1;\n" ::: "memory");
        __syncthreads();

        // ---- QK^T ----
        float sc[8][4];
        #pragma unroll
        for (int i = 0; i < 8; i++)
            #pragma unroll
            for (int j = 0; j < 4; j++) sc[i][j] = 0.f;

        #pragma unroll
        for (int ks = 0; ks < 4; ks++) {
            unsigned aq[4];
            ldsm4(aq, cvta_s(Qs + (warp * 16 + (lane & 15)) * AT_STR
                             + ks * 16 + ((lane >> 4) << 3)));
            #pragma unroll
            for (int nb = 0; nb < 4; nb++) {
                unsigned bk[4];
                // Ks is [key][d] = col-major B (k=d, n=key): non-trans ldmatrix
                int krow = nb * 16 + (lane & 7) + ((lane >> 4) << 3);
                int kcol = ks * 16 + (((lane >> 3) & 1) << 3);
                ldsm4(bk, cvta_s(&Ks[bsel][krow * AT_STR + kcol]));
                mma16816(sc[nb * 2],     aq, bk[0], bk[1]);
                mma16816(sc[nb * 2 + 1], aq, bk[2], bk[3]);
            }
        }

        // ---- diagonal mask ----
        if (tt == tend) {
            int r0 = warp * 16 + g, r1 = r0 + 8;
            #pragma unroll
            for (int nf = 0; nf < 8; nf++) {
                int c0 = nf * 8 + q * 2;
                if (c0     > r0) sc[nf][0] = -1e30f;
                if (c0 + 1 > r0) sc[nf][1] = -1e30f;
                if (c0     > r1) sc[nf][2] = -1e30f;
                if (c0 + 1 > r1) sc[nf][3] = -1e30f;
            }
        }

        // ---- online softmax (log2 domain) ----
        float mt0 = -1e30f, mt1 = -1e30f;
        #pragma unroll
        for (int nf = 0; nf < 8; nf++) {
            mt0 = fmaxf(mt0, fmaxf(sc[nf][0], sc[nf][1]));
            mt1 = fmaxf(mt1, fmaxf(sc[nf][2], sc[nf][3]));
        }
        mt0 = fmaxf(mt0, __shfl_xor_sync(0xffffffffu, mt0, 1));
        mt0 = fmaxf(mt0, __shfl_xor_sync(0xffffffffu, mt0, 2));
        mt1 = fmaxf(mt1, __shfl_xor_sync(0xffffffffu, mt1, 1));
        mt1 = fmaxf(mt1, __shfl_xor_sync(0xffffffffu, mt1, 2));
        float mn0 = fmaxf(m0, mt0), mn1 = fmaxf(m1, mt1);
        float cor0 = ex2f(m0 - mn0), cor1 = ex2f(m1 - mn1);
        m0 = mn0; m1 = mn1;
        float s0 = 0.f, s1 = 0.f;
        #pragma unroll
        for (int nf = 0; nf < 8; nf++) {
            sc[nf][0] = ex2f(sc[nf][0] - mn0);
            sc[nf][1] = ex2f(sc[nf][1] - mn0);
            sc[nf][2] = ex2f(sc[nf][2] - mn1);
            sc[nf][3] = ex2f(sc[nf][3] - mn1);
            s0 += sc[nf][0] + sc[nf][1];
            s1 += sc[nf][2] + sc[nf][3];
        }
        l0 = l0 * cor0 + s0;
        l1 = l1 * cor1 + s1;
        #pragma unroll
        for (int nf = 0; nf < 8; nf++) {
            o_[nf][0] *= cor0; o_[nf][1] *= cor0;
            o_[nf][2] *= cor1; o_[nf][3] *= cor1;
        }

        // ---- P @ V ----
        #pragma unroll
        for (int ks = 0; ks < 4; ks++) {
            unsigned ap[4];
            ap[0] = packh2(sc[2 * ks][0],     sc[2 * ks][1]);
            ap[1] = packh2(sc[2 * ks][2],     sc[2 * ks][3]);
            ap[2] = packh2(sc[2 * ks + 1][0], sc[2 * ks + 1][1]);
            ap[3] = packh2(sc[2 * ks + 1][2], sc[2 * ks + 1][3]);
            #pragma unroll
            for (int nb = 0; nb < 4; nb++) {
                unsigned bv[4];
                // Vs is [key][d] = row-major [k][n]: x4.trans (same as GEMM B path)
                ldsm4t(bv, cvta_s(&Vs[bsel][(ks * 16 + (lane & 15)) * AT_STR
                                            + nb * 16 + ((lane >> 4) << 3)]));
                mma16816(o_[nb * 2],     ap, bv[0], bv[1]);
                mma16816(o_[nb * 2 + 1], ap, bv[2], bv[3]);
            }
        }

        __syncthreads();
        if (tt + 2 <= tend) { KV_ISSUE(tt + 2, bsel); }
        asm volatile("cp.async.commit_group;\n" ::: "memory");
        bsel ^= 1;
    }

    // ---- finalize ----
    l0 += __shfl_xor_sync(0xffffffffu, l0, 1);
    l0 += __shfl_xor_sync(0xffffffffu, l0, 2);
    l1 += __shfl_xor_sync(0xffffffffu, l1, 1);
    l1 += __shfl_xor_sync(0xffffffffu, l1, 2);
    float li0 = 1.f / l0, li1 = 1.f / l1;

    int row0 = n0 + warp * 16 + g;
    h16* p0 = O + ((size_t)(b * NN + row0)) * DIMD + h * DH;
    h16* p1 = O + ((size_t)(b * NN + row0 + 8)) * DIMD + h * DH;
    #pragma unroll
    for (int nf = 0; nf < 8; nf++) {
        *(half2*)(p0 + nf * 8 + q * 2) = __floats2half2_rn(o_[nf][0] * li0, o_[nf][1] * li0);
        *(half2*)(p1 + nf * 8 + q * 2) = __floats2half2_rn(o_[nf][2] * li1, o_[nf][3] * li1);
    }
    #undef KV_ISSUE
}

// ------------------------------ FP16 tensor-core GEMM ------------------------------
#define STAGES 3
#define ASTR 40
#define BSTR 136
#define A_STAGE (128*ASTR)
#define B_STAGE (32*BSTR)
#define GEMM_SMEM (STAGES*(A_STAGE+B_STAGE)*2)

template<bool RES, bool HOUT>
__global__ __launch_bounds__(256) void h16_gemm(
    const h16* __restrict__ A, int lda,
    const h16* __restrict__ B, int ldb,
    const float* __restrict__ R, void* __restrict__ Cv,
    int Nc, int Kb, int Kpad)
{
    extern __shared__ char smem_raw[];
    h16* As = (h16*)smem_raw;
    h16* Bs = (h16*)(smem_raw + (size_t)STAGES * A_STAGE * 2);

    const int t = threadIdx.x;
    const int rowBase = blockIdx.y * 128, colBase = blockIdx.x * 128;
    const int warp = t >> 5, lane = t & 31;
    const int wm = warp >> 2, wn = warp & 3;
    const int q = lane & 3, g = lane >> 2;

    float acc[4][4][4];
    #pragma unroll
    for (int i = 0; i < 4; i++)
        #pragma unroll
        for (int j = 0; j < 4; j++)
            #pragma unroll
            for (int rr = 0; rr < 4; rr++) acc[i][j][rr] = 0.f;

    #define ISSUE(k0, s)                                                        \
    {                                                                           \
        _Pragma("unroll")                                                       \
        for (int i = 0; i < 2; i++) {                                           \
            int c = t + i * 256;                                                \
            int row = c >> 2, cc = c & 3;                                       \
            const h16* src = A + (size_t)(rowBase + row) * lda + (k0) + cc * 8; \
            unsigned dst = cvta_s(As + (s) * A_STAGE + row * ASTR + cc * 8);    \
            asm volatile("cp.async.cg.shared.global [%0], [%1], 16;\n"          \
                         :: "r"(dst), "l"(src));                                \
        }                                                                       \
        _Pragma("unroll")                                                       \
        for (int i = 0; i < 2; i++) {                                           \
            int c = t + i * 256;                                                \
            int row = c >> 4, cc = c & 15;                                      \
            int kidx = (k0) + row;                                              \
            int bytes = (kidx < Kb) ? 16 : 0;                                   \
            const h16* src = B + (size_t)(kidx < Kb ? kidx : 0) * ldb           \
                               + colBase + cc * 8;                              \
            unsigned dst = cvta_s(Bs + (s) * B_STAGE + row * BSTR + cc * 8);    \
            asm volatile("cp.async.cg.shared.global [%0], [%1], 16, %2;\n"      \
                         :: "r"(dst), "l"(src), "r"(bytes));                    \
        }                                                                       \
    }

    #define COMPUTE(s)                                                          \
    {                                                                           \
        _Pragma("unroll")                                                       \
        for (int ks = 0; ks < 32; ks += 16) {                                   \
            unsigned a[4][4], bfr[2][4];                                        \
            _Pragma("unroll")                                                   \
            for (int mf = 0; mf < 4; mf++) {                                    \
                int mrow = wm * 64 + mf * 16 + (lane & 15);                     \
                int colofs = ks + ((lane >> 4) << 3);                           \
                ldsm4(a[mf], cvta_s(As + (s) * A_STAGE + mrow * ASTR + colofs));\
            }                                                                   \
            _Pragma("unroll")                                                   \
            for (int nh = 0; nh < 2; nh++) {                                    \
                int krow = ks + (lane & 15);                                    \
                int col = wn * 32 + nh * 16 + ((lane >> 4) << 3);               \
                ldsm4t(bfr[nh], cvta_s(Bs + (s) * B_STAGE + krow * BSTR + col));\
            }                                                                   \
            _Pragma("unroll")                                                   \
            for (int mf = 0; mf < 4; mf++)                                      \
                _Pragma("unroll")                                               \
                for (int nf = 0; nf < 4; nf++)                                  \
                    mma16816(acc[mf][nf], a[mf],                                \
                             bfr[nf >> 1][(nf & 1) * 2 + 0],                    \
                             bfr[nf >> 1][(nf & 1) * 2 + 1]);                   \
        }                                                                       \
    }

    const int nstage = Kpad / 32;
    ISSUE(0, 0);
    asm volatile("cp.async.commit_group;\n" ::: "memory");
    ISSUE(32, 1);
    asm volatile("cp.async.commit_group;\n" ::: "memory");

    for (int it = 0; it < nstage; it++) {
        asm volatile("cp.async.wait_group 1;\n" ::: "memory");
        __syncthreads();
        int s = it % 3;
        COMPUTE(s);
        if (it + 2 < nstage) {
            int k0 = (it + 2) * 32;
            int s2 = (it + 2) % 3;
            ISSUE(k0, s2);
        }
        asm volatile("cp.async.commit_group;\n" ::: "memory");
    }

    #pragma unroll
    for (int mf = 0; mf < 4; mf++) {
        #pragma unroll
        for (int i = 0; i < 2; i++) {
            int grow = rowBase + wm * 64 + mf * 16 + g + i * 8;
            #pragma unroll
            for (int nf = 0; nf < 4; nf++) {
                int gcol = colBase + wn * 32 + nf * 8 + q * 2;
                if (gcol < Nc) {
                    float v0 = acc[mf][nf][i * 2 + 0];
                    float v1 = acc[mf][nf][i * 2 + 1];
                    if (RES) {
                        const float* Rp = R + (size_t)grow * Nc + gcol;
                        v0 += Rp[0]; v1 += Rp[1];
                    }
                    if (HOUT) {
                        h16* Ch = (h16*)Cv;
                        *(half2*)(Ch + (size_t)grow * Nc + gcol) = __floats2half2_rn(v0, v1);
                    } else {
                        float* Cf = (float*)Cv;
                        *(float2*)(Cf + (size_t)grow * Nc + gcol) = make_float2(v0, v1);
                    }
                }
            }
        }
    }
    #undef ISSUE
    #undef COMPUTE
}

// ------------------------------- GEGLU (fp16 in -> fp16 out, padded) -------------------------------
__global__ __launch_bounds__(256) void geglu_kernel(
    const h16* __restrict__ U, h16* __restrict__ G)
{
    int idx = blockIdx.x * blockDim.x + threadIdx.x;
    const int total = ROWS * GGW2;
    if (idx >= total) return;
    int row = idx / GGW2;
    int c = idx - row * GGW2;
    float val = 0.f;
    if (c < INNER) {
        float a = __half2float(U[(size_t)row * FF1N + c]);
        float g = __half2float(U[(size_t)row * FF1N + INNER + c]);
        float ge = 0.5f * g * (1.f + erff(g * 0.70710678118654752f));
        val = a * ge;
    }
    G[idx] = __float2half_rn(val);
}

// ------------------------------ launch ------------------------------
extern "C" void kernel_launch(void* const* d_in, const int* in_sizes, int n_in,
                              void* d_out, int out_size)
{
    const float* x     = (const float*)d_in[0];
    const float* ln1_w = (const float*)d_in[1];
    const float* ln1_b = (const float*)d_in[2];
    const float* w_qkv = (const float*)d_in[3];
    const float* w_out = (const float*)d_in[4];
    const float* ln2_w = (const float*)d_in[5];
    const float* w_ff1 = (const float*)d_in[6];
    const float* w_ff2 = (const float*)d_in[7];
    float* out = (float*)d_out;

    h16 *p_hh, *p_qh, *p_kh, *p_vh, *p_attnh, *p_uh, *p_ggh;
    h16 *p_wqkv, *p_wout, *p_wff1, *p_wff2;
    float *p_qkv, *p_x1;
    cudaGetSymbolAddress((void**)&p_hh,    g_hh);
    cudaGetSymbolAddress((void**)&p_qkv,   g_qkv);
    cudaGetSymbolAddress((void**)&p_qh,    g_qh);
    cudaGetSymbolAddress((void**)&p_kh,    g_kh);
    cudaGetSymbolAddress((void**)&p_vh,    g_vh);
    cudaGetSymbolAddress((void**)&p_attnh, g_attnh);
    cudaGetSymbolAddress((void**)&p_x1,    g_x1);
    cudaGetSymbolAddress((void**)&p_uh,    g_uh);
    cudaGetSymbolAddress((void**)&p_ggh,   g_ggh);
    cudaGetSymbolAddress((void**)&p_wqkv,  g_wqkv);
    cudaGetSymbolAddress((void**)&p_wout,  g_wout);
    cudaGetSymbolAddress((void**)&p_wff1,  g_wff1);
    cudaGetSymbolAddress((void**)&p_wff2,  g_wff2);

    cudaFuncSetAttribute(h16_gemm<false,false>, cudaFuncAttributeMaxDynamicSharedMemorySize, GEMM_SMEM);
    cudaFuncSetAttribute(h16_gemm<false,true>,  cudaFuncAttributeMaxDynamicSharedMemorySize, GEMM_SMEM);
    cudaFuncSetAttribute(h16_gemm<true,false>,  cudaFuncAttributeMaxDynamicSharedMemorySize, GEMM_SMEM);

    // 0. convert weights to fp16
    {
        int n;
        n = DIMD * QKVN / 4;  f2h_kernel<<<(n + 255) / 256, 256>>>(w_qkv, p_wqkv, n);
        n = DIMD * DIMD / 4;  f2h_kernel<<<(n + 255) / 256, 256>>>(w_out, p_wout, n);
        n = INNER * DIMD / 4; f2h_kernel<<<(n + 255) / 256, 256>>>(w_ff2, p_wff2, n);
        n = DIMD * FF1NP;     f2h_pad_kernel<<<(n + 255) / 256, 256>>>(w_ff1, p_wff1);
    }

    // 1. LN1 -> fp16
    ln_kernel<<<ROWS, 256>>>(x, ln1_w, ln1_b, p_hh);
    // 2. QKV (M=8192, N=3072, K=1024) -> fp32
    h16_gemm<false,false><<<dim3(QKVN / 128, ROWS / 128), 256, GEMM_SMEM>>>(
        p_hh, DIMD, p_wqkv, QKVN, nullptr, p_qkv, QKVN, DIMD, DIMD);
    // 3. rotary + head split -> fp16 q/k/v
    rope_kernel<<<ROWS, 512>>>(p_qkv, p_qh, p_kh, p_vh);
    // 4. tensor-core windowed attention -> fp16
    attn_mma_kernel<<<BB * HEADS * NW * (WW / 64), 128>>>(p_qh, p_kh, p_vh, p_attnh);
    // 5. out proj + residual (M=8192, N=1024, K=1024) -> fp32
    h16_gemm<true,false><<<dim3(DIMD / 128, ROWS / 128), 256, GEMM_SMEM>>>(
        p_attnh, DIMD, p_wout, DIMD, x, p_x1, DIMD, DIMD, DIMD);
    // 6. LN2 -> fp16
    ln_kernel<<<ROWS, 256>>>(p_x1, ln2_w, nullptr, p_hh);
    // 7. FF1 (M=8192, Nc=5460, ldb=5504, K=1024) -> fp16
    h16_gemm<false,true><<<dim3(FF1NP / 128, ROWS / 128), 256, GEMM_SMEM>>>(
        p_hh, DIMD, p_wff1, FF1NP, nullptr, p_uh, FF1N, DIMD, DIMD);
    // 8. GEGLU -> fp16 padded
    {
        int total = ROWS * GGW2;
        geglu_kernel<<<(total + 255) / 256, 256>>>(p_uh, p_ggh);
    }
    // 9. FF2 + residual -> out (M=8192, N=1024, K=2730/2752)
    h16_gemm<true,false><<<dim3(DIMD / 128, ROWS / 128), 256, GEMM_SMEM>>>(
        p_ggh, GGW2, p_wff2, DIMD, p_x1, out, DIMD, INNER, GGW2);
}

// round 6
// speedup vs baseline: 8.8310x; 1.0862x over previous
#include <cuda_runtime.h>
#include <cuda_fp16.h>
#include <math.h>

#define BB 2
#define NN 4096
#define DIMD 1024
#define HEADS 16
#define DH 64
#define WW 512
#define NW (NN/WW)          // 8
#define INNER 2730
#define GGW2 2752           // = FF1NP/2, padded GEGLU output width
#define ROWS (BB*NN)        // 8192
#define QKVN (3*HEADS*DH)   // 3072
#define FF1N (2*INNER)      // 5460
#define FF1NP 5504          // padded/permuted FF1 N (43*128)

typedef __half h16;

// ------------------- scratch (device globals; no allocation) -------------------
__device__ h16   g_hh  [ROWS*DIMD];
__device__ h16   g_qkvh[ROWS*QKVN];
__device__ h16   g_qh  [BB*HEADS*NN*DH];
__device__ h16   g_kh  [BB*HEADS*NN*DH];
__device__ h16   g_vh  [BB*HEADS*NN*DH];
__device__ h16   g_attnh[ROWS*DIMD];
__device__ float g_x1  [ROWS*DIMD];
__device__ h16   g_ggh [ROWS*GGW2];
__device__ h16   g_wqkv[DIMD*QKVN];
__device__ h16   g_wout[DIMD*DIMD];
__device__ h16   g_wff1[DIMD*FF1NP];   // interleaved: col 2c = a_c, 2c+1 = g_c
__device__ h16   g_wff2[INNER*DIMD];

__device__ __forceinline__ unsigned cvta_s(const void* p) {
    return (unsigned)__cvta_generic_to_shared(p);
}
__device__ __forceinline__ float ex2f(float x) {
    float y; asm("ex2.approx.ftz.f32 %0, %1;" : "=f"(y) : "f"(x)); return y;
}
__device__ __forceinline__ void mma16816(float* c, const unsigned* a, unsigned b0, unsigned b1) {
    asm volatile(
        "mma.sync.aligned.m16n8k16.row.col.f32.f16.f16.f32 "
        "{%0,%1,%2,%3}, {%4,%5,%6,%7}, {%8,%9}, {%0,%1,%2,%3};\n"
        : "+f"(c[0]), "+f"(c[1]), "+f"(c[2]), "+f"(c[3])
        : "r"(a[0]), "r"(a[1]), "r"(a[2]), "r"(a[3]), "r"(b0), "r"(b1));
}
__device__ __forceinline__ void ldsm4(unsigned* r, unsigned addr) {
    asm volatile("ldmatrix.sync.aligned.m8n8.x4.shared.b16 {%0,%1,%2,%3}, [%4];\n"
                 : "=r"(r[0]), "=r"(r[1]), "=r"(r[2]), "=r"(r[3]) : "r"(addr));
}
__device__ __forceinline__ void ldsm4t(unsigned* r, unsigned addr) {
    asm volatile("ldmatrix.sync.aligned.m8n8.x4.trans.shared.b16 {%0,%1,%2,%3}, [%4];\n"
                 : "=r"(r[0]), "=r"(r[1]), "=r"(r[2]), "=r"(r[3]) : "r"(addr));
}
__device__ __forceinline__ unsigned packh2(float a, float b) {
    half2 h = __floats2half2_rn(a, b);
    return *(unsigned*)&h;
}

// --------------------------- float -> fp16 convert ---------------------------
__global__ __launch_bounds__(256) void f2h_kernel(
    const float* __restrict__ src, h16* __restrict__ dst, int n4)
{
    int i = blockIdx.x * blockDim.x + threadIdx.x;
    if (i >= n4) return;
    float4 v = ((const float4*)src)[i];
    half2* d = (half2*)dst + i * 2;
    d[0] = __floats2half2_rn(v.x, v.y);
    d[1] = __floats2half2_rn(v.z, v.w);
}

// w_ff1 [DIMD x FF1N] -> fp16 [DIMD x FF1NP] interleaved (a_c, g_c) pairs, zero pad
__global__ __launch_bounds__(256) void f2h_geglu_perm_kernel(
    const float* __restrict__ src, h16* __restrict__ dst)
{
    int idx = blockIdx.x * blockDim.x + threadIdx.x;     // pair index
    const int total = DIMD * (FF1NP / 2);
    if (idx >= total) return;
    int row = idx / (FF1NP / 2);
    int c = idx - row * (FF1NP / 2);
    float a = 0.f, g = 0.f;
    if (c < INNER) {
        const float* rbase = src + (size_t)row * FF1N;
        a = rbase[c];
        g = rbase[INNER + c];
    }
    ((half2*)dst)[(size_t)row * (FF1NP / 2) + c] = __floats2half2_rn(a, g);
}

// ------------------------------- LayerNorm -------------------------------
__global__ __launch_bounds__(256) void ln_kernel(
    const float* __restrict__ X, const float* __restrict__ w,
    const float* __restrict__ b, h16* __restrict__ Y)
{
    __shared__ float sa[8], sb[8];
    int row = blockIdx.x;
    int t = threadIdx.x;
    const float4* xr = (const float4*)(X + (size_t)row * DIMD);
    float4 xv = xr[t];
    float s  = xv.x + xv.y + xv.z + xv.w;
    float sq = xv.x*xv.x + xv.y*xv.y + xv.z*xv.z + xv.w*xv.w;

    int lane = t & 31, wrp = t >> 5;
    #pragma unroll
    for (int o = 16; o; o >>= 1) {
        s  += __shfl_xor_sync(0xffffffffu, s,  o);
        sq += __shfl_xor_sync(0xffffffffu, sq, o);
    }
    if (lane == 0) { sa[wrp] = s; sb[wrp] = sq; }
    __syncthreads();
    if (wrp == 0) {
        s  = (lane < 8) ? sa[lane] : 0.f;
        sq = (lane < 8) ? sb[lane] : 0.f;
        #pragma unroll
        for (int o = 4; o; o >>= 1) {
            s  += __shfl_xor_sync(0xffffffffu, s,  o);
            sq += __shfl_xor_sync(0xffffffffu, sq, o);
        }
        if (lane == 0) { sa[0] = s; sb[0] = sq; }
    }
    __syncthreads();
    float mean = sa[0] * (1.f / DIMD);
    float var  = sb[0] * (1.f / DIMD) - mean * mean;
    float inv  = rsqrtf(var + 1e-5f);

    float4 wv = ((const float4*)w)[t];
    float4 out;
    out.x = (xv.x - mean) * inv * wv.x;
    out.y = (xv.y - mean) * inv * wv.y;
    out.z = (xv.z - mean) * inv * wv.z;
    out.w = (xv.w - mean) * inv * wv.w;
    if (b) {
        float4 bv = ((const float4*)b)[t];
        out.x += bv.x; out.y += bv.y; out.z += bv.z; out.w += bv.w;
    }
    half2* yr = (half2*)(Y + (size_t)row * DIMD);
    yr[2 * t + 0] = __floats2half2_rn(out.x, out.y);
    yr[2 * t + 1] = __floats2half2_rn(out.z, out.w);
}

// ----------------------- rotary + head split (fp16 in/out) -----------------------
#define QSCALE (0.125f * 1.44269504088896341f)
__global__ __launch_bounds__(512) void rope_kernel(
    const h16* __restrict__ QKV, h16* __restrict__ Q,
    h16* __restrict__ K, h16* __restrict__ V)
{
    int row = blockIdx.x;
    int b = row >> 12, n = row & (NN - 1);
    int t = threadIdx.x;
    const h16* base = QKV + (size_t)row * QKVN;

    int h = t >> 5, dj = t & 31;
    float inv = powf(10000.f, -(float)dj * (1.f / 32.f));
    float f = (float)n * inv;
    float sn, cs; sincosf(f, &sn, &cs);

    size_t o = ((size_t)(b * HEADS + h) * NN + n) * DH;
    float x1 = __half2float(base[h * DH + dj]);
    float x2 = __half2float(base[h * DH + dj + 32]);
    Q[o + dj]      = __float2half_rn((x1 * cs - x2 * sn) * QSCALE);
    Q[o + dj + 32] = __float2half_rn((x2 * cs + x1 * sn) * QSCALE);
    x1 = __half2float(base[DIMD + h * DH + dj]);
    x2 = __half2float(base[DIMD + h * DH + dj + 32]);
    K[o + dj]      = __float2half_rn(x1 * cs - x2 * sn);
    K[o + dj + 32] = __float2half_rn(x2 * cs + x1 * sn);
    int c0 = t, c1 = t + 512;
    V[((size_t)(b * HEADS + (c0 >> 6)) * NN + n) * DH + (c0 & 63)] = base[2 * DIMD + c0];
    V[((size_t)(b * HEADS + (c1 >> 6)) * NN + n) * DH + (c1 & 63)] = base[2 * DIMD + c1];
}

// --------------------------- tensor-core windowed attention ---------------------------
#define AT_STR 72
__global__ __launch_bounds__(128) void attn_mma_kernel(
    const h16* __restrict__ Q, const h16* __restrict__ K,
    const h16* __restrict__ V, h16* __restrict__ O)
{
    __shared__ h16 Qs[64 * AT_STR];
    __shared__ h16 Ks[2][64 * AT_STR];
    __shared__ h16 Vs[2][64 * AT_STR];

    int idx = blockIdx.x;
    int qb = idx & 7;
    int wi = (idx >> 3) & 7;
    int h  = (idx >> 6) & 15;
    int b  = idx >> 10;
    int t  = threadIdx.x;
    int warp = t >> 5, lane = t & 31;
    int g = lane >> 2, q = lane & 3;

    const size_t bh = ((size_t)b * HEADS + h) * NN;
    int n0 = wi * WW + qb * 64;
    int tstart = (wi == 0) ? 8 : 0;
    int tend = qb + 8;

    #pragma unroll
    for (int i = 0; i < 4; i++) {
        int c = t + i * 128;
        int row = c >> 3, cc = c & 7;
        unsigned dst = cvta_s(Qs + row * AT_STR + cc * 8);
        const h16* src = Q + (bh + n0 + row) * DH + cc * 8;
        asm volatile("cp.async.cg.shared.global [%0], [%1], 16;\n" :: "r"(dst), "l"(src));
    }

    #define KV_ISSUE(tt_, buf_)                                                  \
    {                                                                            \
        int kg = wi * WW - WW + (tt_) * 64;                                      \
        _Pragma("unroll")                                                        \
        for (int i = 0; i < 4; i++) {                                            \
            int c = t + i * 128;                                                 \
            int row = c >> 3, cc = c & 7;                                        \
            const h16* ks_ = K + (bh + kg + row) * DH + cc * 8;                  \
            const h16* vs_ = V + (bh + kg + row) * DH + cc * 8;                  \
            unsigned kd = cvta_s(&Ks[buf_][row * AT_STR + cc * 8]);              \
            unsigned vd = cvta_s(&Vs[buf_][row * AT_STR + cc * 8]);              \
            asm volatile("cp.async.cg.shared.global [%0], [%1], 16;\n" :: "r"(kd), "l"(ks_)); \
            asm volatile("cp.async.cg.shared.global [%0], [%1], 16;\n" :: "r"(vd), "l"(vs_)); \
        }                                                                        \
    }

    KV_ISSUE(tstart, 0);
    asm volatile("cp.async.commit_group;\n" ::: "memory");
    if (tstart < tend) { KV_ISSUE(tstart + 1, 1); }
    asm volatile("cp.async.commit_group;\n" ::: "memory");

    float o_[8][4];
    #pragma unroll
    for (int i = 0; i < 8; i++)
        #pragma unroll
        for (int j = 0; j < 4; j++) o_[i][j] = 0.f;
    float m0 = -1e30f, m1 = -1e30f, l0 = 0.f, l1 = 0.f;

    int bsel = 0;
    for (int tt = tstart; tt <= tend; tt++) {
        asm volatile("cp.async.wait_group 1;\n" ::: "memory");
        __syncthreads();

        float sc[8][4];
        #pragma unroll
        for (int i = 0; i < 8; i++)
            #pragma unroll
            for (int j = 0; j < 4; j++) sc[i][j] = 0.f;

        #pragma unroll
        for (int ks = 0; ks < 4; ks++) {
            unsigned aq[4];
            ldsm4(aq, cvta_s(Qs + (warp * 16 + (lane & 15)) * AT_STR
                             + ks * 16 + ((lane >> 4) << 3)));
            #pragma unroll
            for (int nb = 0; nb < 4; nb++) {
                unsigned bk[4];
                int krow = nb * 16 + (lane & 7) + ((lane >> 4) << 3);
                int kcol = ks * 16 + (((lane >> 3) & 1) << 3);
                ldsm4(bk, cvta_s(&Ks[bsel][krow * AT_STR + kcol]));
                mma16816(sc[nb * 2],     aq, bk[0], bk[1]);
                mma16816(sc[nb * 2 + 1], aq, bk[2], bk[3]);
            }
        }

        if (tt == tend) {
            int r0 = warp * 16 + g, r1 = r0 + 8;
            #pragma unroll
            for (int nf = 0; nf < 8; nf++) {
                int c0 = nf * 8 + q * 2;
                if (c0     > r0) sc[nf][0] = -1e30f;
                if (c0 + 1 > r0) sc[nf][1] = -1e30f;
                if (c0     > r1) sc[nf][2] = -1e30f;
                if (c0 + 1 > r1) sc[nf][3] = -1e30f;
            }
        }

        float mt0 = -1e30f, mt1 = -1e30f;
        #pragma unroll
        for (int nf = 0; nf < 8; nf++) {
            mt0 = fmaxf(mt0, fmaxf(sc[nf][0], sc[nf][1]));
            mt1 = fmaxf(mt1, fmaxf(sc[nf][2], sc[nf][3]));
        }
        mt0 = fmaxf(mt0, __shfl_xor_sync(0xffffffffu, mt0, 1));
        mt0 = fmaxf(mt0, __shfl_xor_sync(0xffffffffu, mt0, 2));
        mt1 = fmaxf(mt1, __shfl_xor_sync(0xffffffffu, mt1, 1));
        mt1 = fmaxf(mt1, __shfl_xor_sync(0xffffffffu, mt1, 2));
        float mn0 = fmaxf(m0, mt0), mn1 = fmaxf(m1, mt1);
        float cor0 = ex2f(m0 - mn0), cor1 = ex2f(m1 - mn1);
        m0 = mn0; m1 = mn1;
        float s0 = 0.f, s1 = 0.f;
        #pragma unroll
        for (int nf = 0; nf < 8; nf++) {
            sc[nf][0] = ex2f(sc[nf][0] - mn0);
            sc[nf][1] = ex2f(sc[nf][1] - mn0);
            sc[nf][2] = ex2f(sc[nf][2] - mn1);
            sc[nf][3] = ex2f(sc[nf][3] - mn1);
            s0 += sc[nf][0] + sc[nf][1];
            s1 += sc[nf][2] + sc[nf][3];
        }
        l0 = l0 * cor0 + s0;
        l1 = l1 * cor1 + s1;
        #pragma unroll
        for (int nf = 0; nf < 8; nf++) {
            o_[nf][0] *= cor0; o_[nf][1] *= cor0;
            o_[nf][2] *= cor1; o_[nf][3] *= cor1;
        }

        #pragma unroll
        for (int ks = 0; ks < 4; ks++) {
            unsigned ap[4];
            ap[0] = packh2(sc[2 * ks][0],     sc[2 * ks][1]);
            ap[1] = packh2(sc[2 * ks][2],     sc[2 * ks][3]);
            ap[2] = packh2(sc[2 * ks + 1][0], sc[2 * ks + 1][1]);
            ap[3] = packh2(sc[2 * ks + 1][2], sc[2 * ks + 1][3]);
            #pragma unroll
            for (int nb = 0; nb < 4; nb++) {
                unsigned bv[4];
                ldsm4t(bv, cvta_s(&Vs[bsel][(ks * 16 + (lane & 15)) * AT_STR
                                            + nb * 16 + ((lane >> 4) << 3)]));
                mma16816(o_[nb * 2],     ap, bv[0], bv[1]);
                mma16816(o_[nb * 2 + 1], ap, bv[2], bv[3]);
            }
        }

        __syncthreads();
        if (tt + 2 <= tend) { KV_ISSUE(tt + 2, bsel); }
        asm volatile("cp.async.commit_group;\n" ::: "memory");
        bsel ^= 1;
    }

    l0 += __shfl_xor_sync(0xffffffffu, l0, 1);
    l0 += __shfl_xor_sync(0xffffffffu, l0, 2);
    l1 += __shfl_xor_sync(0xffffffffu, l1, 1);
    l1 += __shfl_xor_sync(0xffffffffu, l1, 2);
    float li0 = 1.f / l0, li1 = 1.f / l1;

    int row0 = n0 + warp * 16 + g;
    h16* p0 = O + ((size_t)(b * NN + row0)) * DIMD + h * DH;
    h16* p1 = O + ((size_t)(b * NN + row0 + 8)) * DIMD + h * DH;
    #pragma unroll
    for (int nf = 0; nf < 8; nf++) {
        *(half2*)(p0 + nf * 8 + q * 2) = __floats2half2_rn(o_[nf][0] * li0, o_[nf][1] * li0);
        *(half2*)(p1 + nf * 8 + q * 2) = __floats2half2_rn(o_[nf][2] * li1, o_[nf][3] * li1);
    }
    #undef KV_ISSUE
}

// ------------------------------ FP16 tensor-core GEMM ------------------------------
// OUTMODE: 0 = fp32 out, 1 = fp16 out, 2 = fused GEGLU (pairs (a,g) -> a*gelu(g), fp16,
//          output width Nc/2)
#define STAGES 3
#define ASTR 40
#define BSTR 136
#define A_STAGE (128*ASTR)
#define B_STAGE (32*BSTR)
#define GEMM_SMEM (STAGES*(A_STAGE+B_STAGE)*2)

template<bool RES, int OUTMODE>
__global__ __launch_bounds__(256) void h16_gemm(
    const h16* __restrict__ A, int lda,
    const h16* __restrict__ B, int ldb,
    const float* __restrict__ R, void* __restrict__ Cv,
    int Nc, int Kb, int Kpad)
{
    extern __shared__ char smem_raw[];
    h16* As = (h16*)smem_raw;
    h16* Bs = (h16*)(smem_raw + (size_t)STAGES * A_STAGE * 2);

    const int t = threadIdx.x;
    const int rowBase = blockIdx.y * 128, colBase = blockIdx.x * 128;
    const int warp = t >> 5, lane = t & 31;
    const int wm = warp >> 2, wn = warp & 3;
    const int q = lane & 3, g = lane >> 2;

    float acc[4][4][4];
    #pragma unroll
    for (int i = 0; i < 4; i++)
        #pragma unroll
        for (int j = 0; j < 4; j++)
            #pragma unroll
            for (int rr = 0; rr < 4; rr++) acc[i][j][rr] = 0.f;

    #define ISSUE(k0, s)                                                        \
    {                                                                           \
        _Pragma("unroll")                                                       \
        for (int i = 0; i < 2; i++) {                                           \
            int c = t + i * 256;                                                \
            int row = c >> 2, cc = c & 3;                                       \
            const h16* src = A + (size_t)(rowBase + row) * lda + (k0) + cc * 8; \
            unsigned dst = cvta_s(As + (s) * A_STAGE + row * ASTR + cc * 8);    \
            asm volatile("cp.async.cg.shared.global [%0], [%1], 16;\n"          \
                         :: "r"(dst), "l"(src));                                \
        }                                                                       \
        _Pragma("unroll")                                                       \
        for (int i = 0; i < 2; i++) {                                           \
            int c = t + i * 256;                                                \
            int row = c >> 4, cc = c & 15;                                      \
            int kidx = (k0) + row;                                              \
            int bytes = (kidx < Kb) ? 16 : 0;                                   \
            const h16* src = B + (size_t)(kidx < Kb ? kidx : 0) * ldb           \
                               + colBase + cc * 8;                              \
            unsigned dst = cvta_s(Bs + (s) * B_STAGE + row * BSTR + cc * 8);    \
            asm volatile("cp.async.cg.shared.global [%0], [%1], 16, %2;\n"      \
                         :: "r"(dst), "l"(src), "r"(bytes));                    \
        }                                                                       \
    }

    #define COMPUTE(s)                                                          \
    {                                                                           \
        _Pragma("unroll")                                                       \
        for (int ks = 0; ks < 32; ks += 16) {                                   \
            unsigned a[4][4], bfr[2][4];                                        \
            _Pragma("unroll")                                                   \
            for (int mf = 0; mf < 4; mf++) {                                    \
                int mrow = wm * 64 + mf * 16 + (lane & 15);                     \
                int colofs = ks + ((lane >> 4) << 3);                           \
                ldsm4(a[mf], cvta_s(As + (s) * A_STAGE + mrow * ASTR + colofs));\
            }                                                                   \
            _Pragma("unroll")                                                   \
            for (int nh = 0; nh < 2; nh++) {                                    \
                int krow = ks + (lane & 15);                                    \
                int col = wn * 32 + nh * 16 + ((lane >> 4) << 3);               \
                ldsm4t(bfr[nh], cvta_s(Bs + (s) * B_STAGE + krow * BSTR + col));\
            }                                                                   \
            _Pragma("unroll")                                                   \
            for (int mf = 0; mf < 4; mf++)                                      \
                _Pragma("unroll")                                               \
                for (int nf = 0; nf < 4; nf++)                                  \
                    mma16816(acc[mf][nf], a[mf],                                \
                             bfr[nf >> 1][(nf & 1) * 2 + 0],                    \
                             bfr[nf >> 1][(nf & 1) * 2 + 1]);                   \
        }                                                                       \
    }

    const int nstage = Kpad / 32;
    ISSUE(0, 0);
    asm volatile("cp.async.commit_group;\n" ::: "memory");
    ISSUE(32, 1);
    asm volatile("cp.async.commit_group;\n" ::: "memory");

    for (int it = 0; it < nstage; it++) {
        asm volatile("cp.async.wait_group 1;\n" ::: "memory");
        __syncthreads();
        int s = it % 3;
        COMPUTE(s);
        if (it + 2 < nstage) {
            int k0 = (it + 2) * 32;
            int s2 = (it + 2) % 3;
            ISSUE(k0, s2);
        }
        asm volatile("cp.async.commit_group;\n" ::: "memory");
    }

    #pragma unroll
    for (int mf = 0; mf < 4; mf++) {
        #pragma unroll
        for (int i = 0; i < 2; i++) {
            int grow = rowBase + wm * 64 + mf * 16 + g + i * 8;
            #pragma unroll
            for (int nf = 0; nf < 4; nf++) {
                int gcol = colBase + wn * 32 + nf * 8 + q * 2;
                if (gcol < Nc) {
                    float v0 = acc[mf][nf][i * 2 + 0];
                    float v1 = acc[mf][nf][i * 2 + 1];
                    if (RES) {
                        const float* Rp = R + (size_t)grow * Nc + gcol;
                        v0 += Rp[0]; v1 += Rp[1];
                    }
                    if (OUTMODE == 0) {
                        float* Cf = (float*)Cv;
                        *(float2*)(Cf + (size_t)grow * Nc + gcol) = make_float2(v0, v1);
                    } else if (OUTMODE == 1) {
                        h16* Ch = (h16*)Cv;
                        *(half2*)(Ch + (size_t)grow * Nc + gcol) = __floats2half2_rn(v0, v1);
                    } else {
                        // GEGLU: (v0, v1) = (a_c, g_c), out col = gcol/2, width Nc/2
                        float ge = 0.5f * v1 * (1.f + erff(v1 * 0.70710678118654752f));
                        h16* Ch = (h16*)Cv;
                        Ch[(size_t)grow * (Nc / 2) + (gcol >> 1)] = __float2half_rn(v0 * ge);
                    }
                }
            }
        }
    }
    #undef ISSUE
    #undef COMPUTE
}

// ------------------------------ launch ------------------------------
extern "C" void kernel_launch(void* const* d_in, const int* in_sizes, int n_in,
                              void* d_out, int out_size)
{
    const float* x     = (const float*)d_in[0];
    const float* ln1_w = (const float*)d_in[1];
    const float* ln1_b = (const float*)d_in[2];
    const float* w_qkv = (const float*)d_in[3];
    const float* w_out = (const float*)d_in[4];
    const float* ln2_w = (const float*)d_in[5];
    const float* w_ff1 = (const float*)d_in[6];
    const float* w_ff2 = (const float*)d_in[7];
    float* out = (float*)d_out;

    h16 *p_hh, *p_qkvh, *p_qh, *p_kh, *p_vh, *p_attnh, *p_ggh;
    h16 *p_wqkv, *p_wout, *p_wff1, *p_wff2;
    float *p_x1;
    cudaGetSymbolAddress((void**)&p_hh,    g_hh);
    cudaGetSymbolAddress((void**)&p_qkvh,  g_qkvh);
    cudaGetSymbolAddress((void**)&p_qh,    g_qh);
    cudaGetSymbolAddress((void**)&p_kh,    g_kh);
    cudaGetSymbolAddress((void**)&p_vh,    g_vh);
    cudaGetSymbolAddress((void**)&p_attnh, g_attnh);
    cudaGetSymbolAddress((void**)&p_x1,    g_x1);
    cudaGetSymbolAddress((void**)&p_ggh,   g_ggh);
    cudaGetSymbolAddress((void**)&p_wqkv,  g_wqkv);
    cudaGetSymbolAddress((void**)&p_wout,  g_wout);
    cudaGetSymbolAddress((void**)&p_wff1,  g_wff1);
    cudaGetSymbolAddress((void**)&p_wff2,  g_wff2);

    cudaFuncSetAttribute(h16_gemm<false,0>, cudaFuncAttributeMaxDynamicSharedMemorySize, GEMM_SMEM);
    cudaFuncSetAttribute(h16_gemm<false,1>, cudaFuncAttributeMaxDynamicSharedMemorySize, GEMM_SMEM);
    cudaFuncSetAttribute(h16_gemm<false,2>, cudaFuncAttributeMaxDynamicSharedMemorySize, GEMM_SMEM);
    cudaFuncSetAttribute(h16_gemm<true,0>,  cudaFuncAttributeMaxDynamicSharedMemorySize, GEMM_SMEM);

    // 0. convert weights to fp16 (w_ff1 also interleave-permuted for fused GEGLU)
    {
        int n;
        n = DIMD * QKVN / 4;   f2h_kernel<<<(n + 255) / 256, 256>>>(w_qkv, p_wqkv, n);
        n = DIMD * DIMD / 4;   f2h_kernel<<<(n + 255) / 256, 256>>>(w_out, p_wout, n);
        n = INNER * DIMD / 4;  f2h_kernel<<<(n + 255) / 256, 256>>>(w_ff2, p_wff2, n);
        n = DIMD * (FF1NP/2);  f2h_geglu_perm_kernel<<<(n + 255) / 256, 256>>>(w_ff1, p_wff1);
    }

    // 1. LN1 -> fp16
    ln_kernel<<<ROWS, 256>>>(x, ln1_w, ln1_b, p_hh);
    // 2. QKV (M=8192, N=3072, K=1024) -> fp16
    h16_gemm<false,1><<<dim3(QKVN / 128, ROWS / 128), 256, GEMM_SMEM>>>(
        p_hh, DIMD, p_wqkv, QKVN, nullptr, p_qkvh, QKVN, DIMD, DIMD);
    // 3. rotary + head split (fp16 in/out)
    rope_kernel<<<ROWS, 512>>>(p_qkvh, p_qh, p_kh, p_vh);
    // 4. tensor-core windowed attention -> fp16
    attn_mma_kernel<<<BB * HEADS * NW * (WW / 64), 128>>>(p_qh, p_kh, p_vh, p_attnh);
    // 5. out proj + residual (M=8192, N=1024, K=1024) -> fp32
    h16_gemm<true,0><<<dim3(DIMD / 128, ROWS / 128), 256, GEMM_SMEM>>>(
        p_attnh, DIMD, p_wout, DIMD, x, p_x1, DIMD, DIMD, DIMD);
    // 6. LN2 -> fp16
    ln_kernel<<<ROWS, 256>>>(p_x1, ln2_w, nullptr, p_hh);
    // 7. FF1 + fused GEGLU (M=8192, Nc=5504 interleaved, K=1024) -> gg fp16 [8192 x 2752]
    h16_gemm<false,2><<<dim3(FF1NP / 128, ROWS / 128), 256, GEMM_SMEM>>>(
        p_hh, DIMD, p_wff1, FF1NP, nullptr, p_ggh, FF1NP, DIMD, DIMD);
    // 8. FF2 + residual -> out (M=8192, N=1024, K=2752 incl. exact zero pad)
    h16_gemm<true,0><<<dim3(DIMD / 128, ROWS / 128), 256, GEMM_SMEM>>>(
        p_ggh, GGW2, p_wff2, DIMD, p_x1, out, DIMD, INNER, GGW2);
}